// round 9
// baseline (speedup 1.0000x reference)
#include <cuda_runtime.h>
#include <cuda_fp16.h>
#include <cstdint>

#define NT 1024
#define NH 2048
#define NI 2048
#define NEXP 16
#define NTOP 4
#define NSLOT (NT*NTOP)
#define NBLKS 64
#define ALPHA 1.702f
#define FLIMIT 7.0f
#define NCH 32               // K chunks of 64 halves

#define STRB 144             // bytes per smem row (128B data + 16B pad)
#define ABYTES (128*STRB)    // 18432
#define BBYTES (256*STRB)    // 36864
#define STAGEB (ABYTES+BBYTES) // 55296
#define DSMEM_BYTES (4*STAGEB) // 221184

// ---------------- scratch ----------------
__device__ int    g_tok_exp[NSLOT];
__device__ float  g_tok_w[NSLOT];
__device__ int    g_counts[NEXP];
__device__ int    g_offsets[NEXP];
__device__ int    g_token_list[NSLOT];
__device__ int    g_slot_of[NSLOT];
__device__ __half g_xh[(size_t)NT * NH];       // fp16 x
__device__ __half g_hbuf[(size_t)NSLOT * NI];  // fp16 h
__device__ float  g_obuf[(size_t)NSLOT * NH];

// ---------------- helpers ----------------
__device__ __forceinline__ uint32_t f2h2(float a, float b){
    __half2 h = __floats2half2_rn(a, b);
    return *(uint32_t*)&h;
}
__device__ __forceinline__ uint32_t smem_u32(const void* p){
    uint32_t a;
    asm("{ .reg .u64 t; cvta.to.shared.u64 t, %1; cvt.u32.u64 %0, t; }" : "=r"(a) : "l"(p));
    return a;
}
__device__ __forceinline__ void cp16(uint32_t dst, const void* src){
    asm volatile("cp.async.cg.shared.global [%0], [%1], 16;" :: "r"(dst), "l"(src) : "memory");
}
__device__ __forceinline__ void cp_commit(){ asm volatile("cp.async.commit_group;" ::: "memory"); }
__device__ __forceinline__ void cp_wait2(){ asm volatile("cp.async.wait_group 2;" ::: "memory"); }

__device__ __forceinline__ void ldsm4(uint32_t& r0, uint32_t& r1, uint32_t& r2, uint32_t& r3, uint32_t addr){
    asm volatile("ldmatrix.sync.aligned.m8n8.x4.shared.b16 {%0,%1,%2,%3}, [%4];"
        : "=r"(r0), "=r"(r1), "=r"(r2), "=r"(r3) : "r"(addr));
}
__device__ __forceinline__ void mma_f16(float d[4], const uint32_t a[4], const uint32_t b[2]){
    asm volatile("mma.sync.aligned.m16n8k16.row.col.f32.f16.f16.f32 "
        "{%0,%1,%2,%3},{%4,%5,%6,%7},{%8,%9},{%0,%1,%2,%3};"
        : "+f"(d[0]),"+f"(d[1]),"+f"(d[2]),"+f"(d[3])
        : "r"(a[0]),"r"(a[1]),"r"(a[2]),"r"(a[3]),"r"(b[0]),"r"(b[1]));
}
__device__ __forceinline__ float act_fn(float g, float u){
    g = fminf(g, FLIMIT);
    u = fminf(fmaxf(u, -FLIMIT), FLIMIT);
    float sig = __fdividef(1.f, 1.f + __expf(-ALPHA*g));
    return (u + 1.f) * (g * sig);
}
__device__ __forceinline__ void stsB(uint32_t addr, float4 lo, float4 hi, float s){
    uint32_t a = f2h2(lo.x*s, lo.y*s);
    uint32_t b = f2h2(lo.z*s, lo.w*s);
    uint32_t c = f2h2(hi.x*s, hi.y*s);
    uint32_t d = f2h2(hi.z*s, hi.w*s);
    asm volatile("st.shared.v4.b32 [%0], {%1,%2,%3,%4};" :: "r"(addr),"r"(a),"r"(b),"r"(c),"r"(d) : "memory");
}

// fragment load (64x64 warp tile) into buffer f
#define LDF(f, ks) do { \
    _Pragma("unroll") \
    for (int m2=0;m2<4;m2++) \
        ldsm4(af[f][m2][0],af[f][m2][1],af[f][m2][2],af[f][m2][3], stg + lmA0 + m2*2304 + (ks)*32); \
    _Pragma("unroll") \
    for (int j=0;j<4;j++) \
        ldsm4(bf[f][2*j][0],bf[f][2*j][1],bf[f][2*j+1][0],bf[f][2*j+1][1], stg + lmB0 + j*2304 + (ks)*32); \
} while(0)

#define MMF(f) do { \
    _Pragma("unroll") \
    for (int nt=0;nt<8;nt++) \
        _Pragma("unroll") \
        for (int m2=0;m2<4;m2++) mma_f16(acc[m2][nt], af[f][m2], bf[f][nt]); \
} while(0)

// ---------------- K0: x -> fp16 ----------------
__global__ void prep_x_kernel(const float* __restrict__ x)
{
    const int i = blockIdx.x * blockDim.x + threadIdx.x;
    float4 v = *(const float4*)(x + (size_t)i*4);
    uint2 o;
    o.x = f2h2(v.x, v.y);
    o.y = f2h2(v.z, v.w);
    *(uint2*)(g_xh + (size_t)i*4) = o;
}

// ---------------- K1: router ----------------
__global__ void router_kernel(const float* __restrict__ x,
                              const float* __restrict__ rw,
                              const float* __restrict__ rb)
{
    __shared__ float sx[NH];
    __shared__ float slog[NEXP];
    const int t = blockIdx.x;
    for (int i = threadIdx.x; i < NH; i += blockDim.x)
        sx[i] = x[(size_t)t*NH + i];
    __syncthreads();
    const int w = threadIdx.x >> 5;
    const int lane = threadIdx.x & 31;
    const float* wr = rw + (size_t)w*NH;
    float s = 0.f;
    for (int i = lane; i < NH; i += 32) s += sx[i]*wr[i];
    #pragma unroll
    for (int o=16;o>0;o>>=1) s += __shfl_xor_sync(0xffffffffu, s, o);
    if (lane==0) slog[w] = s + rb[w];
    __syncthreads();
    if (threadIdx.x==0){
        float v[NEXP];
        #pragma unroll
        for (int e=0;e<NEXP;e++) v[e]=slog[e];
        int idx[NTOP]; float val[NTOP];
        #pragma unroll
        for (int k=0;k<NTOP;k++){
            int bi=0; float bv=v[0];
            #pragma unroll
            for (int e=1;e<NEXP;e++){ if (v[e]>bv){bv=v[e];bi=e;} }
            idx[k]=bi; val[k]=bv; v[bi]=-3.4e38f;
        }
        float mx=val[0], ssum=0.f, ev[NTOP];
        #pragma unroll
        for(int k=0;k<NTOP;k++){ ev[k]=expf(val[k]-mx); ssum+=ev[k]; }
        float inv = 1.f/ssum;
        #pragma unroll
        for(int k=0;k<NTOP;k++){
            g_tok_exp[t*NTOP+k]=idx[k];
            g_tok_w[t*NTOP+k]=ev[k]*inv;
        }
    }
}

// ---------------- K2: build per-expert token lists ----------------
__global__ void build_lists_kernel()
{
    __shared__ int sc[NEXP], so[NEXP], scur[NEXP];
    const int t = threadIdx.x;
    if (t < NEXP) sc[t]=0;
    __syncthreads();
    int ex[NTOP];
    #pragma unroll
    for (int k=0;k<NTOP;k++){ ex[k]=g_tok_exp[t*NTOP+k]; atomicAdd(&sc[ex[k]],1); }
    __syncthreads();
    if (t==0){
        int acc=0;
        for(int e=0;e<NEXP;e++){ so[e]=acc; acc+=sc[e]; }
    }
    __syncthreads();
    if (t<NEXP){ g_counts[t]=sc[t]; g_offsets[t]=so[t]; scur[t]=so[t]; }
    __syncthreads();
    #pragma unroll
    for (int k=0;k<NTOP;k++){
        int slot = atomicAdd(&scur[ex[k]],1);
        g_token_list[slot]=t;
        g_slot_of[t*NTOP+k]=slot;
    }
}

// ================= GEMM cores: 256 thr, 8 warps, warp tile 64x64 =================
// BM=128 rows, BN=256 smem-B rows. wm=(wid&1)*64, wn=(wid>>1)*64.
// 4-stage ring; A cp.async; B LDG->dequant->fp16 STS one chunk ahead.

// ---------------- K3: gate+up GEMM + activation ----------------
// B rows 0-127: gate cols n0..n0+127 ; rows 128-255: up same cols.
__global__ void __launch_bounds__(256,1)
gateup_kernel(const float* __restrict__ gblk, const float* __restrict__ gscl,
              const float* __restrict__ gbia,
              const float* __restrict__ ublk, const float* __restrict__ uscl,
              const float* __restrict__ ubia)
{
    extern __shared__ float smf[];
    __shared__ int sTok[128];
    __shared__ float sGb[128], sUb[128];

    const int e   = blockIdx.y >> 3;
    const int mt  = blockIdx.y & 7;
    const int M   = g_counts[e];
    if (mt*128 >= M) return;
    const int Mrows = min(128, M - mt*128);
    const int off = g_offsets[e];
    const int n0  = blockIdx.x * 128;
    const int tid = threadIdx.x;
    const int wid = tid >> 5;
    const int lane = tid & 31;

    if (tid < 128){
        int ml = mt*128 + tid; if (ml > M-1) ml = M-1;
        sTok[tid] = g_token_list[off + ml];
        sGb[tid] = gbia[(size_t)e*NI + n0 + tid];
        sUb[tid] = ubia[(size_t)e*NI + n0 + tid];
    }
    __syncthreads();

    const uint32_t base = smem_u32(smf);
    const int r0 = tid >> 3;      // 0..31
    const int s  = tid & 7;
    const int sh = s >> 2;

    const __half* srcA[4];
    #pragma unroll
    for (int j=0;j<4;j++)
        srcA[j] = g_xh + (size_t)sTok[r0 + 32*j]*NH + s*8;
    const uint32_t offA0 = (uint32_t)(r0*STRB + s*16);

    const float* pG  = gblk + ((size_t)e*NI + n0 + r0)*NH + s*8;
    const float* pU  = ublk + ((size_t)e*NI + n0 + r0)*NH + s*8;
    const float* pSg = gscl + ((size_t)e*NI + n0 + r0)*NBLKS;
    const float* pSu = uscl + ((size_t)e*NI + n0 + r0)*NBLKS;
    const uint32_t offB0 = (uint32_t)(ABYTES + r0*STRB + s*16);

    const int wm = (wid & 1) * 64;
    const int wn = (wid >> 1) * 64;   // 0,64: gate ; 128,192: up
    const int fr = lane >> 2;
    const int fc = lane & 3;
    const bool active = (wm < Mrows);

    const uint32_t lmA0 = (uint32_t)((wm + (lane & 15))*STRB + (lane >> 4)*16);
    const uint32_t lmB0 = (uint32_t)(ABYTES + (wn + ((lane>>4)&1)*8 + (lane&7))*STRB + ((lane>>3)&1)*16);

    float acc[4][8][4];
    #pragma unroll
    for (int a=0;a<4;a++)
        #pragma unroll
        for (int b=0;b<8;b++)
            #pragma unroll
            for (int c=0;c<4;c++) acc[a][b][c]=0.f;

    uint32_t af[2][4][4], bf[2][8][2];
    float4 vlo[2], vhi[2]; float vsv[2];

#define BPTRG(j) (((j)<4) ? (pG + (j)*(32*NH)) : (pU + ((j)-4)*(32*NH)))
#define SPTRG(j) (((j)<4) ? (pSg + (j)*(32*NBLKS)) : (pSu + ((j)-4)*(32*NBLKS)))
#define LDG_G(q, j, kb_, ksc_) do{ const float* bp_ = BPTRG(j) + (kb_); \
    vlo[q]=*(const float4*)bp_; vhi[q]=*(const float4*)(bp_+4); vsv[q]=SPTRG(j)[(ksc_)]; }while(0)

    // prologue: A0,A1,A2 cp.async ; B0 staged synchronously
    #pragma unroll
    for (int st=0; st<3; st++){
        #pragma unroll
        for (int j=0;j<4;j++) cp16(base + st*STAGEB + offA0 + j*4608, srcA[j] + st*64);
        cp_commit();
    }
    #pragma unroll
    for (int j=0;j<8;j++){
        LDG_G(0, j, 0, sh);
        stsB(base + offB0 + j*4608, vlo[0], vhi[0], vsv[0]);
    }
    cp_wait2();
    __syncthreads();

    for (int kc=0; kc<NCH; kc++){
        const uint32_t stg = base + (kc&3)*STAGEB;
        const uint32_t nst = base + ((kc+1)&3)*STAGEB;
        const bool more = (kc+1 < NCH);
        if (kc+3 < NCH){
            const uint32_t dst = base + ((kc+3)&3)*STAGEB;
            const int ka = (kc+3)*64;
            #pragma unroll
            for (int j=0;j<4;j++) cp16(dst + offA0 + j*4608, srcA[j] + ka);
        }
        cp_commit();

        const int kb  = (kc+1)*64;
        const int ksc = 2*(kc+1) + sh;

        if (more){ LDG_G(0,0,kb,ksc); LDG_G(1,1,kb,ksc); }
        if (active){ LDF(0, 0); LDF(1, 1); MMF(0); }
        if (more){
            stsB(nst + offB0 + 0*4608, vlo[0], vhi[0], vsv[0]);
            stsB(nst + offB0 + 1*4608, vlo[1], vhi[1], vsv[1]);
            LDG_G(0,2,kb,ksc); LDG_G(1,3,kb,ksc);
        }
        if (active){ LDF(0, 2); MMF(1); }
        if (more){
            stsB(nst + offB0 + 2*4608, vlo[0], vhi[0], vsv[0]);
            stsB(nst + offB0 + 3*4608, vlo[1], vhi[1], vsv[1]);
            LDG_G(0,4,kb,ksc); LDG_G(1,5,kb,ksc);
        }
        if (active){ LDF(1, 3); MMF(0); }
        if (more){
            stsB(nst + offB0 + 4*4608, vlo[0], vhi[0], vsv[0]);
            stsB(nst + offB0 + 5*4608, vlo[1], vhi[1], vsv[1]);
            LDG_G(0,6,kb,ksc); LDG_G(1,7,kb,ksc);
        }
        if (active){ MMF(1); }
        if (more){
            stsB(nst + offB0 + 6*4608, vlo[0], vhi[0], vsv[0]);
            stsB(nst + offB0 + 7*4608, vlo[1], vhi[1], vsv[1]);
        }
        cp_wait2();
        __syncthreads();
    }
#undef BPTRG
#undef SPTRG
#undef LDG_G

    // epilogue: gate warps (wn<128) stash raw accs to G; up warps combine -> fp16 h.
    float* G = smf;   // 128 x 132 floats = 67584 B
    if (wn < 128 && active){
        #pragma unroll
        for (int m2=0;m2<4;m2++){
            #pragma unroll
            for (int nt=0;nt<8;nt++){
                const int rl = wm + m2*16 + fr;
                const int c  = wn + nt*8 + fc*2;
                *(float2*)&G[rl*132 + c]     = make_float2(acc[m2][nt][0], acc[m2][nt][1]);
                *(float2*)&G[(rl+8)*132 + c] = make_float2(acc[m2][nt][2], acc[m2][nt][3]);
            }
        }
    }
    __syncthreads();
    if (wn >= 128 && active){
        #pragma unroll
        for (int m2=0;m2<4;m2++){
            #pragma unroll
            for (int nt=0;nt<8;nt++){
                const int rl = wm + m2*16 + fr;
                const int cu = (wn-128) + nt*8 + fc*2;
                const float gb0 = sGb[cu], gb1 = sGb[cu+1];
                const float ub0 = sUb[cu], ub1 = sUb[cu+1];
                if (rl < Mrows){
                    float2 gp = *(float2*)&G[rl*132 + cu];
                    float h0 = act_fn(gp.x+gb0, acc[m2][nt][0]+ub0);
                    float h1 = act_fn(gp.y+gb1, acc[m2][nt][1]+ub1);
                    *(uint32_t*)&g_hbuf[(size_t)(off + mt*128 + rl)*NI + n0 + cu] = f2h2(h0,h1);
                }
                if (rl+8 < Mrows){
                    float2 gp = *(float2*)&G[(rl+8)*132 + cu];
                    float h0 = act_fn(gp.x+gb0, acc[m2][nt][2]+ub0);
                    float h1 = act_fn(gp.y+gb1, acc[m2][nt][3]+ub1);
                    *(uint32_t*)&g_hbuf[(size_t)(off + mt*128 + rl+8)*NI + n0 + cu] = f2h2(h0,h1);
                }
            }
        }
    }
}

// ---------------- K4: down GEMM + bias ----------------
__global__ void __launch_bounds__(256,1)
down_kernel(const float* __restrict__ dblk, const float* __restrict__ dscl,
            const float* __restrict__ dbia)
{
    extern __shared__ float smf[];
    __shared__ float sDb[256];

    const int e   = blockIdx.y >> 3;
    const int mt  = blockIdx.y & 7;
    const int M   = g_counts[e];
    if (mt*128 >= M) return;
    const int Mrows = min(128, M - mt*128);
    const int off = g_offsets[e];
    const int n0  = blockIdx.x * 256;
    const int tid = threadIdx.x;
    const int wid = tid >> 5;
    const int lane = tid & 31;

    sDb[tid] = dbia[(size_t)e*NH + n0 + tid];
    __syncthreads();

    const uint32_t base = smem_u32(smf);
    const int r0 = tid >> 3;
    const int s  = tid & 7;
    const int sh = s >> 2;

    const __half* srcA[4];
    #pragma unroll
    for (int j=0;j<4;j++){
        int ml = mt*128 + r0 + 32*j; if (ml > M-1) ml = M-1;
        srcA[j] = g_hbuf + (size_t)(off + ml)*NI + s*8;
    }
    const uint32_t offA0 = (uint32_t)(r0*STRB + s*16);

    const float* pBd = dblk + ((size_t)e*NH + n0 + r0)*NI + s*8;
    const float* pSd = dscl + ((size_t)e*NH + n0 + r0)*NBLKS;
    const uint32_t offB0 = (uint32_t)(ABYTES + r0*STRB + s*16);

    const int wm = (wid & 1) * 64;
    const int wn = (wid >> 1) * 64;
    const int fr = lane >> 2;
    const int fc = lane & 3;
    const bool active = (wm < Mrows);

    const uint32_t lmA0 = (uint32_t)((wm + (lane & 15))*STRB + (lane >> 4)*16);
    const uint32_t lmB0 = (uint32_t)(ABYTES + (wn + ((lane>>4)&1)*8 + (lane&7))*STRB + ((lane>>3)&1)*16);

    float acc[4][8][4];
    #pragma unroll
    for (int a=0;a<4;a++)
        #pragma unroll
        for (int b=0;b<8;b++)
            #pragma unroll
            for (int c=0;c<4;c++) acc[a][b][c]=0.f;

    uint32_t af[2][4][4], bf[2][8][2];
    float4 vlo[2], vhi[2]; float vsv[2];

#define LDG_D(q, j, kb_, ksc_) do{ const float* bp_ = pBd + (j)*(32*NI) + (kb_); \
    vlo[q]=*(const float4*)bp_; vhi[q]=*(const float4*)(bp_+4); vsv[q]=(pSd + (j)*(32*NBLKS))[(ksc_)]; }while(0)

    #pragma unroll
    for (int st=0; st<3; st++){
        #pragma unroll
        for (int j=0;j<4;j++) cp16(base + st*STAGEB + offA0 + j*4608, srcA[j] + st*64);
        cp_commit();
    }
    #pragma unroll
    for (int j=0;j<8;j++){
        LDG_D(0, j, 0, sh);
        stsB(base + offB0 + j*4608, vlo[0], vhi[0], vsv[0]);
    }
    cp_wait2();
    __syncthreads();

    for (int kc=0; kc<NCH; kc++){
        const uint32_t stg = base + (kc&3)*STAGEB;
        const uint32_t nst = base + ((kc+1)&3)*STAGEB;
        const bool more = (kc+1 < NCH);
        if (kc+3 < NCH){
            const uint32_t dst = base + ((kc+3)&3)*STAGEB;
            const int ka = (kc+3)*64;
            #pragma unroll
            for (int j=0;j<4;j++) cp16(dst + offA0 + j*4608, srcA[j] + ka);
        }
        cp_commit();

        const int kb  = (kc+1)*64;
        const int ksc = 2*(kc+1) + sh;

        if (more){ LDG_D(0,0,kb,ksc); LDG_D(1,1,kb,ksc); }
        if (active){ LDF(0, 0); LDF(1, 1); MMF(0); }
        if (more){
            stsB(nst + offB0 + 0*4608, vlo[0], vhi[0], vsv[0]);
            stsB(nst + offB0 + 1*4608, vlo[1], vhi[1], vsv[1]);
            LDG_D(0,2,kb,ksc); LDG_D(1,3,kb,ksc);
        }
        if (active){ LDF(0, 2); MMF(1); }
        if (more){
            stsB(nst + offB0 + 2*4608, vlo[0], vhi[0], vsv[0]);
            stsB(nst + offB0 + 3*4608, vlo[1], vhi[1], vsv[1]);
            LDG_D(0,4,kb,ksc); LDG_D(1,5,kb,ksc);
        }
        if (active){ LDF(1, 3); MMF(0); }
        if (more){
            stsB(nst + offB0 + 4*4608, vlo[0], vhi[0], vsv[0]);
            stsB(nst + offB0 + 5*4608, vlo[1], vhi[1], vsv[1]);
            LDG_D(0,6,kb,ksc); LDG_D(1,7,kb,ksc);
        }
        if (active){ MMF(1); }
        if (more){
            stsB(nst + offB0 + 6*4608, vlo[0], vhi[0], vsv[0]);
            stsB(nst + offB0 + 7*4608, vlo[1], vhi[1], vsv[1]);
        }
        cp_wait2();
        __syncthreads();
    }
#undef LDG_D

    if (active){
        #pragma unroll
        for (int m2=0;m2<4;m2++){
            #pragma unroll
            for (int nt=0;nt<8;nt++){
                const int rl = wm + m2*16 + fr;
                const int cg = wn + nt*8 + fc*2;
                const float b0 = sDb[cg], b1 = sDb[cg+1];
                if (rl < Mrows){
                    *(float2*)&g_obuf[(size_t)(off + mt*128 + rl)*NH + n0 + cg] =
                        make_float2(acc[m2][nt][0]+b0, acc[m2][nt][1]+b1);
                }
                if (rl+8 < Mrows){
                    *(float2*)&g_obuf[(size_t)(off + mt*128 + rl+8)*NH + n0 + cg] =
                        make_float2(acc[m2][nt][2]+b0, acc[m2][nt][3]+b1);
                }
            }
        }
    }
}

// ---------------- K5: weighted combine ----------------
__global__ void combine_kernel(float* __restrict__ out)
{
    const int t = blockIdx.x;
    int sl[NTOP]; float w[NTOP];
    #pragma unroll
    for (int k=0;k<NTOP;k++){ sl[k]=g_slot_of[t*NTOP+k]; w[k]=g_tok_w[t*NTOP+k]; }
    for (int i = threadIdx.x; i < NH/4; i += blockDim.x){
        float4 a = make_float4(0.f,0.f,0.f,0.f);
        #pragma unroll
        for (int k=0;k<NTOP;k++){
            float4 v = *(const float4*)&g_obuf[(size_t)sl[k]*NH + i*4];
            a.x += w[k]*v.x; a.y += w[k]*v.y; a.z += w[k]*v.z; a.w += w[k]*v.w;
        }
        *(float4*)&out[(size_t)t*NH + i*4] = a;
    }
}

// ---------------- launch ----------------
extern "C" void kernel_launch(void* const* d_in, const int* in_sizes, int n_in,
                              void* d_out, int out_size)
{
    const float* x    = (const float*)d_in[0];
    const float* rw   = (const float*)d_in[1];
    const float* rb   = (const float*)d_in[2];
    const float* gblk = (const float*)d_in[3];
    const float* gscl = (const float*)d_in[4];
    const float* gbia = (const float*)d_in[5];
    const float* ublk = (const float*)d_in[6];
    const float* uscl = (const float*)d_in[7];
    const float* ubia = (const float*)d_in[8];
    const float* dblk = (const float*)d_in[9];
    const float* dscl = (const float*)d_in[10];
    const float* dbia = (const float*)d_in[11];
    float* out = (float*)d_out;

    cudaFuncSetAttribute(gateup_kernel, cudaFuncAttributeMaxDynamicSharedMemorySize, DSMEM_BYTES);
    cudaFuncSetAttribute(down_kernel,   cudaFuncAttributeMaxDynamicSharedMemorySize, DSMEM_BYTES);

    prep_x_kernel<<<(NT*NH/4)/256, 256>>>(x);
    router_kernel<<<NT, 512>>>(x, rw, rb);
    build_lists_kernel<<<1, NT>>>();
    gateup_kernel<<<dim3(NI/128, NEXP*8), 256, DSMEM_BYTES>>>(gblk, gscl, gbia, ublk, uscl, ubia);
    down_kernel<<<dim3(NH/256, NEXP*8), 256, DSMEM_BYTES>>>(dblk, dscl, dbia);
    combine_kernel<<<NT, 256>>>(out);
}

// round 10
// speedup vs baseline: 1.2620x; 1.2620x over previous
#include <cuda_runtime.h>
#include <cuda_fp16.h>
#include <cstdint>

#define NT 1024
#define NH 2048
#define NI 2048
#define NEXP 16
#define NTOP 4
#define NSLOT (NT*NTOP)
#define NBLKS 64
#define ALPHA 1.702f
#define FLIMIT 7.0f
#define NCH 32               // K chunks of 64 halves

#define STRB 144             // bytes per smem row (128B data + 16B pad)
#define ABYTES (128*STRB)    // 18432
#define STAGEB (2*ABYTES)    // 36864 per stage (A+B)
#define NSTG 3
#define DSMEM_BYTES (NSTG*STAGEB)  // 110592

// ---------------- scratch ----------------
__device__ int    g_tok_exp[NSLOT];
__device__ float  g_tok_w[NSLOT];
__device__ int    g_counts[NEXP];
__device__ int    g_offsets[NEXP];
__device__ int    g_token_list[NSLOT];
__device__ int    g_slot_of[NSLOT];
__device__ __half g_xh[(size_t)NT * NH];       // fp16 x
__device__ __half g_hbuf[(size_t)NSLOT * NI];  // fp16 h
__device__ float  g_obuf[(size_t)NSLOT * NH];

// ---------------- helpers ----------------
__device__ __forceinline__ uint32_t f2h2(float a, float b){
    __half2 h = __floats2half2_rn(a, b);
    return *(uint32_t*)&h;
}
__device__ __forceinline__ uint32_t smem_u32(const void* p){
    uint32_t a;
    asm("{ .reg .u64 t; cvta.to.shared.u64 t, %1; cvt.u32.u64 %0, t; }" : "=r"(a) : "l"(p));
    return a;
}
__device__ __forceinline__ void cp16(uint32_t dst, const void* src){
    asm volatile("cp.async.cg.shared.global [%0], [%1], 16;" :: "r"(dst), "l"(src) : "memory");
}
__device__ __forceinline__ void cp_commit(){ asm volatile("cp.async.commit_group;" ::: "memory"); }
__device__ __forceinline__ void cp_wait1(){ asm volatile("cp.async.wait_group 1;" ::: "memory"); }

__device__ __forceinline__ void ldsm4(uint32_t& r0, uint32_t& r1, uint32_t& r2, uint32_t& r3, uint32_t addr){
    asm volatile("ldmatrix.sync.aligned.m8n8.x4.shared.b16 {%0,%1,%2,%3}, [%4];"
        : "=r"(r0), "=r"(r1), "=r"(r2), "=r"(r3) : "r"(addr));
}
__device__ __forceinline__ void mma_f16(float d[4], const uint32_t a[4], const uint32_t b[2]){
    asm volatile("mma.sync.aligned.m16n8k16.row.col.f32.f16.f16.f32 "
        "{%0,%1,%2,%3},{%4,%5,%6,%7},{%8,%9},{%0,%1,%2,%3};"
        : "+f"(d[0]),"+f"(d[1]),"+f"(d[2]),"+f"(d[3])
        : "r"(a[0]),"r"(a[1]),"r"(a[2]),"r"(a[3]),"r"(b[0]),"r"(b[1]));
}
__device__ __forceinline__ float act_fn(float g, float u){
    g = fminf(g, FLIMIT);
    u = fminf(fmaxf(u, -FLIMIT), FLIMIT);
    float sig = __fdividef(1.f, 1.f + __expf(-ALPHA*g));
    return (u + 1.f) * (g * sig);
}
__device__ __forceinline__ void stsB(uint32_t addr, float4 lo, float4 hi, float s){
    uint32_t a = f2h2(lo.x*s, lo.y*s);
    uint32_t b = f2h2(lo.z*s, lo.w*s);
    uint32_t c = f2h2(hi.x*s, hi.y*s);
    uint32_t d = f2h2(hi.z*s, hi.w*s);
    asm volatile("st.shared.v4.b32 [%0], {%1,%2,%3,%4};" :: "r"(addr),"r"(a),"r"(b),"r"(c),"r"(d) : "memory");
}

// ---------------- K1: router (+ fp16 x emit) ----------------
__global__ void router_kernel(const float* __restrict__ x,
                              const float* __restrict__ rw,
                              const float* __restrict__ rb)
{
    __shared__ float sx[NH];
    __shared__ float slog[NEXP];
    const int t = blockIdx.x;
    for (int i = threadIdx.x; i < NH; i += blockDim.x)
        sx[i] = x[(size_t)t*NH + i];
    __syncthreads();
    // emit fp16 copy of this token row
    for (int i = threadIdx.x; i < NH/2; i += blockDim.x){
        *(uint32_t*)&g_xh[(size_t)t*NH + i*2] = f2h2(sx[i*2], sx[i*2+1]);
    }
    const int w = threadIdx.x >> 5;
    const int lane = threadIdx.x & 31;
    const float* wr = rw + (size_t)w*NH;
    float s = 0.f;
    for (int i = lane; i < NH; i += 32) s += sx[i]*wr[i];
    #pragma unroll
    for (int o=16;o>0;o>>=1) s += __shfl_xor_sync(0xffffffffu, s, o);
    if (lane==0) slog[w] = s + rb[w];
    __syncthreads();
    if (threadIdx.x==0){
        float v[NEXP];
        #pragma unroll
        for (int e=0;e<NEXP;e++) v[e]=slog[e];
        int idx[NTOP]; float val[NTOP];
        #pragma unroll
        for (int k=0;k<NTOP;k++){
            int bi=0; float bv=v[0];
            #pragma unroll
            for (int e=1;e<NEXP;e++){ if (v[e]>bv){bv=v[e];bi=e;} }
            idx[k]=bi; val[k]=bv; v[bi]=-3.4e38f;
        }
        float mx=val[0], ssum=0.f, ev[NTOP];
        #pragma unroll
        for(int k=0;k<NTOP;k++){ ev[k]=expf(val[k]-mx); ssum+=ev[k]; }
        float inv = 1.f/ssum;
        #pragma unroll
        for(int k=0;k<NTOP;k++){
            g_tok_exp[t*NTOP+k]=idx[k];
            g_tok_w[t*NTOP+k]=ev[k]*inv;
        }
    }
}

// ---------------- K2: build per-expert token lists ----------------
__global__ void build_lists_kernel()
{
    __shared__ int sc[NEXP], so[NEXP], scur[NEXP];
    const int t = threadIdx.x;
    if (t < NEXP) sc[t]=0;
    __syncthreads();
    int ex[NTOP];
    #pragma unroll
    for (int k=0;k<NTOP;k++){ ex[k]=g_tok_exp[t*NTOP+k]; atomicAdd(&sc[ex[k]],1); }
    __syncthreads();
    if (t==0){
        int acc=0;
        for(int e=0;e<NEXP;e++){ so[e]=acc; acc+=sc[e]; }
    }
    __syncthreads();
    if (t<NEXP){ g_counts[t]=sc[t]; g_offsets[t]=so[t]; scur[t]=so[t]; }
    __syncthreads();
    #pragma unroll
    for (int k=0;k<NTOP;k++){
        int slot = atomicAdd(&scur[ex[k]],1);
        g_token_list[slot]=t;
        g_slot_of[t*NTOP+k]=slot;
    }
}

// ================= GEMM cores (fp16, BK=64): 256 thr, 8 warps =================
// Stage: [A 128 rows x 144B][B 128 rows x 144B]; 3 stages.

// ---------------- K3: gate+up GEMM + activation ----------------
// B rows 0-63: gate cols n0..n0+63; rows 64-127: up same cols.
// Warp layout: wm=(wid&3)*32 rows, wn=(wid>>2)*32 cols; each warp computes
// BOTH gate[32x32] and up[32x32] for its patch (shared A frags, direct epilogue).
__global__ void __launch_bounds__(256,2)
gateup_kernel(const float* __restrict__ gblk, const float* __restrict__ gscl,
              const float* __restrict__ gbia,
              const float* __restrict__ ublk, const float* __restrict__ uscl,
              const float* __restrict__ ubia)
{
    extern __shared__ float smf[];
    __shared__ int sTok[128];
    __shared__ float sGb[64], sUb[64];

    const int e   = blockIdx.y >> 3;
    const int mt  = blockIdx.y & 7;
    const int M   = g_counts[e];
    if (mt*128 >= M) return;
    const int Mrows = min(128, M - mt*128);
    const int off = g_offsets[e];
    const int n0  = blockIdx.x * 64;
    const int tid = threadIdx.x;
    const int wid = tid >> 5;
    const int lane = tid & 31;

    if (tid < 128){
        int ml = mt*128 + tid; if (ml > M-1) ml = M-1;
        sTok[tid] = g_token_list[off + ml];
    }
    if (tid < 64){
        sGb[tid] = gbia[(size_t)e*NI + n0 + tid];
        sUb[tid] = ubia[(size_t)e*NI + n0 + tid];
    }
    __syncthreads();

    const uint32_t smemBase = smem_u32(smf);
    const int r0s = tid >> 3;
    const int s  = tid & 7;
    const int sh = s >> 2;

    // A staging: 4 cp.async per thread (seg id = tid + 256j; r=id>>3, s=id&7)
    const __half* srcA[4]; uint32_t offA[4];
    #pragma unroll
    for (int j=0;j<4;j++){
        int r = r0s + 32*j;
        srcA[j] = g_xh + (size_t)sTok[r]*NH + s*8;
        offA[j] = (uint32_t)(r*STRB + s*16);
    }
    // B staging: 4 seg-groups per thread; rows<64 gate (j=0,1), >=64 up (j=2,3)
    const float* pB[4]; const float* pS[4]; uint32_t offB[4];
    #pragma unroll
    for (int j=0;j<4;j++){
        int r = r0s + 32*j;
        size_t grow = (size_t)e*NI + (size_t)(n0 + (r & 63));
        const float* blk = (r < 64) ? gblk : ublk;
        const float* scl = (r < 64) ? gscl : uscl;
        pB[j] = blk + grow*NH + s*8;
        pS[j] = scl + grow*NBLKS;
        offB[j] = (uint32_t)(ABYTES + r*STRB + s*16);
    }

    const int wm = (wid & 3) * 32;
    const int wn = (wid >> 2) * 32;    // 0 or 32: col patch (both gate & up)
    const int fr = lane >> 2;
    const int fc = lane & 3;
    const bool active = (wm < Mrows);

    const uint32_t lmA0 = (uint32_t)((wm + (lane & 15))*STRB + (lane >> 4)*16);
    // B frag base: gate rows wn.., up rows 64+wn..
    const uint32_t lmBg = (uint32_t)(ABYTES + (wn + ((lane>>4)&1)*8 + (lane&7))*STRB + ((lane>>3)&1)*16);

    float accg[2][4][4], accu[2][4][4];
    #pragma unroll
    for (int a=0;a<2;a++)
        #pragma unroll
        for (int b=0;b<4;b++)
            #pragma unroll
            for (int c=0;c<4;c++){ accg[a][b][c]=0.f; accu[a][b][c]=0.f; }

    // prologue
    {
        #pragma unroll
        for (int j=0;j<4;j++) cp16(smemBase + offA[j], srcA[j]);
        cp_commit();
        #pragma unroll
        for (int j=0;j<4;j++) cp16(smemBase + STAGEB + offA[j], srcA[j] + 64);
        cp_commit();
        #pragma unroll
        for (int j=0;j<4;j++){
            float4 lo = *(const float4*)(pB[j]);
            float4 hi = *(const float4*)(pB[j] + 4);
            stsB(smemBase + offB[j], lo, hi, pS[j][sh]);
        }
        cp_wait1();
    }
    __syncthreads();

#define GU_MMA(ks) do { \
    uint32_t af[2][4]; \
    _Pragma("unroll") \
    for (int m2=0;m2<2;m2++) \
        ldsm4(af[m2][0],af[m2][1],af[m2][2],af[m2][3], stg + lmA0 + m2*2304 + (ks)*32); \
    uint32_t bg[4][2], bu[4][2]; \
    _Pragma("unroll") \
    for (int j=0;j<2;j++){ \
        ldsm4(bg[2*j][0],bg[2*j][1],bg[2*j+1][0],bg[2*j+1][1], stg + lmBg + j*2304 + (ks)*32); \
        ldsm4(bu[2*j][0],bu[2*j][1],bu[2*j+1][0],bu[2*j+1][1], stg + lmBg + 9216 + j*2304 + (ks)*32); \
    } \
    _Pragma("unroll") \
    for (int nt=0;nt<4;nt++) \
        _Pragma("unroll") \
        for (int m2=0;m2<2;m2++){ \
            mma_f16(accg[m2][nt], af[m2], bg[nt]); \
            mma_f16(accu[m2][nt], af[m2], bu[nt]); \
        } \
} while(0)

    for (int kc=0; kc<NCH; kc++){
        const uint32_t stg = smemBase + (kc%NSTG)*STAGEB;
        const uint32_t s1b = smemBase + ((kc+1)%NSTG)*STAGEB;
        const bool more = (kc+1 < NCH);
        if (kc+2 < NCH){
            const uint32_t dst = smemBase + ((kc+2)%NSTG)*STAGEB;
            const int ka = (kc+2)*64;
            #pragma unroll
            for (int j=0;j<4;j++) cp16(dst + offA[j], srcA[j] + ka);
        }
        cp_commit();

        const int kb  = (kc+1)*64;
        const int ksc = 2*(kc+1) + sh;
        float4 lo0, hi0, lo1, hi1; float sc0 = 0.f, sc1 = 0.f;
        if (more){
            lo0 = *(const float4*)(pB[0] + kb); hi0 = *(const float4*)(pB[0] + kb + 4);
            lo1 = *(const float4*)(pB[1] + kb); hi1 = *(const float4*)(pB[1] + kb + 4);
            sc0 = pS[0][ksc]; sc1 = pS[1][ksc];
        }
        if (active){ GU_MMA(0); GU_MMA(1); }
        if (more){
            stsB(s1b + offB[0], lo0, hi0, sc0);
            stsB(s1b + offB[1], lo1, hi1, sc1);
            lo0 = *(const float4*)(pB[2] + kb); hi0 = *(const float4*)(pB[2] + kb + 4);
            lo1 = *(const float4*)(pB[3] + kb); hi1 = *(const float4*)(pB[3] + kb + 4);
            sc0 = pS[2][ksc]; sc1 = pS[3][ksc];
        }
        if (active){ GU_MMA(2); GU_MMA(3); }
        if (more){
            stsB(s1b + offB[2], lo0, hi0, sc0);
            stsB(s1b + offB[3], lo1, hi1, sc1);
        }
        cp_wait1();
        __syncthreads();
    }
#undef GU_MMA

    // epilogue: direct (warp owns both gate and up accs)
    if (active){
        #pragma unroll
        for (int m2=0;m2<2;m2++){
            #pragma unroll
            for (int nt=0;nt<4;nt++){
                const int rl = wm + m2*16 + fr;
                const int cu = wn + nt*8 + fc*2;
                const float gb0 = sGb[cu], gb1 = sGb[cu+1];
                const float ub0 = sUb[cu], ub1 = sUb[cu+1];
                if (rl < Mrows){
                    float h0 = act_fn(accg[m2][nt][0]+gb0, accu[m2][nt][0]+ub0);
                    float h1 = act_fn(accg[m2][nt][1]+gb1, accu[m2][nt][1]+ub1);
                    *(uint32_t*)&g_hbuf[(size_t)(off + mt*128 + rl)*NI + n0 + cu] = f2h2(h0,h1);
                }
                if (rl+8 < Mrows){
                    float h0 = act_fn(accg[m2][nt][2]+gb0, accu[m2][nt][2]+ub0);
                    float h1 = act_fn(accg[m2][nt][3]+gb1, accu[m2][nt][3]+ub1);
                    *(uint32_t*)&g_hbuf[(size_t)(off + mt*128 + rl+8)*NI + n0 + cu] = f2h2(h0,h1);
                }
            }
        }
    }
}

// ---------------- K4: down GEMM + bias (R7-proven) ----------------
__global__ void __launch_bounds__(256,2)
down_kernel(const float* __restrict__ dblk, const float* __restrict__ dscl,
            const float* __restrict__ dbia)
{
    extern __shared__ float smf[];
    __shared__ float sDb[128];

    const int e   = blockIdx.y >> 3;
    const int mt  = blockIdx.y & 7;
    const int M   = g_counts[e];
    if (mt*128 >= M) return;
    const int Mrows = min(128, M - mt*128);
    const int off = g_offsets[e];
    const int n0  = blockIdx.x * 128;
    const int tid = threadIdx.x;
    const int wid = tid >> 5;
    const int lane = tid & 31;

    if (tid < 128) sDb[tid] = dbia[(size_t)e*NH + n0 + tid];
    __syncthreads();

    const uint32_t smemBase = smem_u32(smf);
    const int r0s = tid >> 3;
    const int s  = tid & 7;
    const int sh = s >> 2;

    const __half* srcA[4]; uint32_t offA[4];
    #pragma unroll
    for (int j=0;j<4;j++){
        int r = r0s + 32*j;
        int ml = mt*128 + r; if (ml > M-1) ml = M-1;
        srcA[j] = g_hbuf + (size_t)(off + ml)*NI + s*8;
        offA[j] = (uint32_t)(r*STRB + s*16);
    }
    const float* pB[4]; const float* pS[4]; uint32_t offB[4];
    #pragma unroll
    for (int j=0;j<4;j++){
        int r = r0s + 32*j;
        size_t grow = (size_t)e*NH + (size_t)(n0 + r);
        pB[j] = dblk + grow*NI + s*8;
        pS[j] = dscl + grow*NBLKS;
        offB[j] = (uint32_t)(ABYTES + r*STRB + s*16);
    }

    const int wm = (wid & 3) * 32;
    const int wn = (wid >> 2) * 64;
    const int fr = lane >> 2;
    const int fc = lane & 3;
    const bool active = (wm < Mrows);

    const uint32_t lmA0 = (uint32_t)((wm + (lane & 15))*STRB + (lane >> 4)*16);
    const uint32_t lmB0 = (uint32_t)(ABYTES + (wn + ((lane>>4)&1)*8 + (lane&7))*STRB + ((lane>>3)&1)*16);

    float acc[2][8][4];
    #pragma unroll
    for (int a=0;a<2;a++)
        #pragma unroll
        for (int b=0;b<8;b++)
            #pragma unroll
            for (int c=0;c<4;c++) acc[a][b][c]=0.f;

    {
        #pragma unroll
        for (int j=0;j<4;j++) cp16(smemBase + offA[j], srcA[j]);
        cp_commit();
        #pragma unroll
        for (int j=0;j<4;j++) cp16(smemBase + STAGEB + offA[j], srcA[j] + 64);
        cp_commit();
        #pragma unroll
        for (int j=0;j<4;j++){
            float4 lo = *(const float4*)(pB[j]);
            float4 hi = *(const float4*)(pB[j] + 4);
            stsB(smemBase + offB[j], lo, hi, pS[j][sh]);
        }
        cp_wait1();
    }
    __syncthreads();

#define DN_MMA(ks) do { \
    uint32_t af[2][4]; \
    _Pragma("unroll") \
    for (int m2=0;m2<2;m2++) \
        ldsm4(af[m2][0],af[m2][1],af[m2][2],af[m2][3], stg + lmA0 + m2*2304 + (ks)*32); \
    uint32_t bf[8][2]; \
    _Pragma("unroll") \
    for (int j=0;j<4;j++) \
        ldsm4(bf[2*j][0],bf[2*j][1],bf[2*j+1][0],bf[2*j+1][1], stg + lmB0 + j*2304 + (ks)*32); \
    _Pragma("unroll") \
    for (int nt=0;nt<8;nt++) \
        _Pragma("unroll") \
        for (int m2=0;m2<2;m2++) mma_f16(acc[m2][nt], af[m2], bf[nt]); \
} while(0)

    for (int kc=0; kc<NCH; kc++){
        const uint32_t stg = smemBase + (kc%NSTG)*STAGEB;
        const uint32_t s1b = smemBase + ((kc+1)%NSTG)*STAGEB;
        const bool more = (kc+1 < NCH);
        if (kc+2 < NCH){
            const uint32_t dst = smemBase + ((kc+2)%NSTG)*STAGEB;
            const int ka = (kc+2)*64;
            #pragma unroll
            for (int j=0;j<4;j++) cp16(dst + offA[j], srcA[j] + ka);
        }
        cp_commit();

        const int kb  = (kc+1)*64;
        const int ksc = 2*(kc+1) + sh;
        float4 lo0, hi0, lo1, hi1; float sc0 = 0.f, sc1 = 0.f;
        if (more){
            lo0 = *(const float4*)(pB[0] + kb); hi0 = *(const float4*)(pB[0] + kb + 4);
            lo1 = *(const float4*)(pB[1] + kb); hi1 = *(const float4*)(pB[1] + kb + 4);
            sc0 = pS[0][ksc]; sc1 = pS[1][ksc];
        }
        if (active){ DN_MMA(0); DN_MMA(1); }
        if (more){
            stsB(s1b + offB[0], lo0, hi0, sc0);
            stsB(s1b + offB[1], lo1, hi1, sc1);
            lo0 = *(const float4*)(pB[2] + kb); hi0 = *(const float4*)(pB[2] + kb + 4);
            lo1 = *(const float4*)(pB[3] + kb); hi1 = *(const float4*)(pB[3] + kb + 4);
            sc0 = pS[2][ksc]; sc1 = pS[3][ksc];
        }
        if (active){ DN_MMA(2); DN_MMA(3); }
        if (more){
            stsB(s1b + offB[2], lo0, hi0, sc0);
            stsB(s1b + offB[3], lo1, hi1, sc1);
        }
        cp_wait1();
        __syncthreads();
    }
#undef DN_MMA

    if (active){
        #pragma unroll
        for (int m2=0;m2<2;m2++){
            #pragma unroll
            for (int nt=0;nt<8;nt++){
                const int rl = wm + m2*16 + fr;
                const int cg = wn + nt*8 + fc*2;
                const float b0 = sDb[cg], b1 = sDb[cg+1];
                if (rl < Mrows){
                    *(float2*)&g_obuf[(size_t)(off + mt*128 + rl)*NH + n0 + cg] =
                        make_float2(acc[m2][nt][0]+b0, acc[m2][nt][1]+b1);
                }
                if (rl+8 < Mrows){
                    *(float2*)&g_obuf[(size_t)(off + mt*128 + rl+8)*NH + n0 + cg] =
                        make_float2(acc[m2][nt][2]+b0, acc[m2][nt][3]+b1);
                }
            }
        }
    }
}

// ---------------- K5: weighted combine ----------------
__global__ void combine_kernel(float* __restrict__ out)
{
    const int t = blockIdx.x;
    int sl[NTOP]; float w[NTOP];
    #pragma unroll
    for (int k=0;k<NTOP;k++){ sl[k]=g_slot_of[t*NTOP+k]; w[k]=g_tok_w[t*NTOP+k]; }
    for (int i = threadIdx.x; i < NH/4; i += blockDim.x){
        float4 a = make_float4(0.f,0.f,0.f,0.f);
        #pragma unroll
        for (int k=0;k<NTOP;k++){
            float4 v = *(const float4*)&g_obuf[(size_t)sl[k]*NH + i*4];
            a.x += w[k]*v.x; a.y += w[k]*v.y; a.z += w[k]*v.z; a.w += w[k]*v.w;
        }
        *(float4*)&out[(size_t)t*NH + i*4] = a;
    }
}

// ---------------- launch ----------------
extern "C" void kernel_launch(void* const* d_in, const int* in_sizes, int n_in,
                              void* d_out, int out_size)
{
    const float* x    = (const float*)d_in[0];
    const float* rw   = (const float*)d_in[1];
    const float* rb   = (const float*)d_in[2];
    const float* gblk = (const float*)d_in[3];
    const float* gscl = (const float*)d_in[4];
    const float* gbia = (const float*)d_in[5];
    const float* ublk = (const float*)d_in[6];
    const float* uscl = (const float*)d_in[7];
    const float* ubia = (const float*)d_in[8];
    const float* dblk = (const float*)d_in[9];
    const float* dscl = (const float*)d_in[10];
    const float* dbia = (const float*)d_in[11];
    float* out = (float*)d_out;

    cudaFuncSetAttribute(gateup_kernel, cudaFuncAttributeMaxDynamicSharedMemorySize, DSMEM_BYTES);
    cudaFuncSetAttribute(down_kernel,   cudaFuncAttributeMaxDynamicSharedMemorySize, DSMEM_BYTES);

    router_kernel<<<NT, 512>>>(x, rw, rb);
    build_lists_kernel<<<1, NT>>>();
    gateup_kernel<<<dim3(NI/64, NEXP*8), 256, DSMEM_BYTES>>>(gblk, gscl, gbia, ublk, uscl, ubia);
    down_kernel<<<dim3(NH/128, NEXP*8), 256, DSMEM_BYTES>>>(dblk, dscl, dbia);
    combine_kernel<<<NT, 256>>>(out);
}

// round 12
// speedup vs baseline: 1.3119x; 1.0395x over previous
#include <cuda_runtime.h>
#include <cuda_fp16.h>
#include <cstdint>

#define NT 1024
#define NH 2048
#define NI 2048
#define NEXP 16
#define NTOP 4
#define NSLOT (NT*NTOP)
#define NBLKS 64
#define ALPHA 1.702f
#define FLIMIT 7.0f
#define NCH 32               // K chunks of 64 halves

#define STRB 144             // bytes per smem row (128B data + 16B pad)
#define ABYTES (128*STRB)    // 18432
#define STAGEB (2*ABYTES)    // 36864 per stage (A+B)
#define NSTG 3
#define DSMEM_BYTES (NSTG*STAGEB)  // 110592

#define WELEM ((size_t)NEXP*NI*NH)   // 67108864 elements per weight matrix

// ---------------- scratch ----------------
__device__ int    g_tok_exp[NSLOT];
__device__ float  g_tok_w[NSLOT];
__device__ int    g_counts[NEXP];
__device__ int    g_offsets[NEXP];
__device__ int    g_token_list[NSLOT];
__device__ int    g_slot_of[NSLOT];
__device__ __half g_xh[(size_t)NT * NH];       // fp16 x
__device__ __half g_hbuf[(size_t)NSLOT * NI];  // fp16 h
__device__ float  g_obuf[(size_t)NSLOT * NH];
__device__ __half g_gw16[WELEM];               // dequantized gate weights
__device__ __half g_uw16[WELEM];               // dequantized up weights
__device__ __half g_dw16[WELEM];               // dequantized down weights

// ---------------- helpers ----------------
__device__ __forceinline__ uint32_t f2h2(float a, float b){
    __half2 h = __floats2half2_rn(a, b);
    return *(uint32_t*)&h;
}
__device__ __forceinline__ uint32_t smem_u32(const void* p){
    uint32_t a;
    asm("{ .reg .u64 t; cvta.to.shared.u64 t, %1; cvt.u32.u64 %0, t; }" : "=r"(a) : "l"(p));
    return a;
}
__device__ __forceinline__ void cp16(uint32_t dst, const void* src){
    asm volatile("cp.async.cg.shared.global [%0], [%1], 16;" :: "r"(dst), "l"(src) : "memory");
}
__device__ __forceinline__ void cp_commit(){ asm volatile("cp.async.commit_group;" ::: "memory"); }
__device__ __forceinline__ void cp_wait1(){ asm volatile("cp.async.wait_group 1;" ::: "memory"); }

__device__ __forceinline__ void ldsm4(uint32_t& r0, uint32_t& r1, uint32_t& r2, uint32_t& r3, uint32_t addr){
    asm volatile("ldmatrix.sync.aligned.m8n8.x4.shared.b16 {%0,%1,%2,%3}, [%4];"
        : "=r"(r0), "=r"(r1), "=r"(r2), "=r"(r3) : "r"(addr));
}
__device__ __forceinline__ void mma_f16(float d[4], const uint32_t a[4], const uint32_t b[2]){
    asm volatile("mma.sync.aligned.m16n8k16.row.col.f32.f16.f16.f32 "
        "{%0,%1,%2,%3},{%4,%5,%6,%7},{%8,%9},{%0,%1,%2,%3};"
        : "+f"(d[0]),"+f"(d[1]),"+f"(d[2]),"+f"(d[3])
        : "r"(a[0]),"r"(a[1]),"r"(a[2]),"r"(a[3]),"r"(b[0]),"r"(b[1]));
}
__device__ __forceinline__ float act_fn(float g, float u){
    g = fminf(g, FLIMIT);
    u = fminf(fmaxf(u, -FLIMIT), FLIMIT);
    float sig = __fdividef(1.f, 1.f + __expf(-ALPHA*g));
    return (u + 1.f) * (g * sig);
}

// ---------------- K0: dequantize one weight matrix to fp16 ----------------
// one thread per 8 consecutive elements (all within one 32-elem scale block)
__global__ void __launch_bounds__(256)
dequant_kernel(const float* __restrict__ blk, const float* __restrict__ scl,
               __half* __restrict__ out)
{
    const size_t gid = (size_t)blockIdx.x * blockDim.x + threadIdx.x;
    const size_t base = gid * 8;
    const float s = __ldg(&scl[gid >> 2]);
    float4 a = *(const float4*)(blk + base);
    float4 b = *(const float4*)(blk + base + 4);
    uint4 o;
    o.x = f2h2(a.x*s, a.y*s);
    o.y = f2h2(a.z*s, a.w*s);
    o.z = f2h2(b.x*s, b.y*s);
    o.w = f2h2(b.z*s, b.w*s);
    *(uint4*)(out + base) = o;
}

// ---------------- K1: router (+ fp16 x emit) ----------------
__global__ void router_kernel(const float* __restrict__ x,
                              const float* __restrict__ rw,
                              const float* __restrict__ rb)
{
    __shared__ float sx[NH];
    __shared__ float slog[NEXP];
    const int t = blockIdx.x;
    for (int i = threadIdx.x; i < NH; i += blockDim.x)
        sx[i] = x[(size_t)t*NH + i];
    __syncthreads();
    for (int i = threadIdx.x; i < NH/2; i += blockDim.x){
        *(uint32_t*)&g_xh[(size_t)t*NH + i*2] = f2h2(sx[i*2], sx[i*2+1]);
    }
    const int w = threadIdx.x >> 5;
    const int lane = threadIdx.x & 31;
    const float* wr = rw + (size_t)w*NH;
    float s = 0.f;
    for (int i = lane; i < NH; i += 32) s += sx[i]*wr[i];
    #pragma unroll
    for (int o=16;o>0;o>>=1) s += __shfl_xor_sync(0xffffffffu, s, o);
    if (lane==0) slog[w] = s + rb[w];
    __syncthreads();
    if (threadIdx.x==0){
        float v[NEXP];
        #pragma unroll
        for (int e=0;e<NEXP;e++) v[e]=slog[e];
        int idx[NTOP]; float val[NTOP];
        #pragma unroll
        for (int k=0;k<NTOP;k++){
            int bi=0; float bv=v[0];
            #pragma unroll
            for (int e=1;e<NEXP;e++){ if (v[e]>bv){bv=v[e];bi=e;} }
            idx[k]=bi; val[k]=bv; v[bi]=-3.4e38f;
        }
        float mx=val[0], ssum=0.f, ev[NTOP];
        #pragma unroll
        for(int k=0;k<NTOP;k++){ ev[k]=expf(val[k]-mx); ssum+=ev[k]; }
        float inv = 1.f/ssum;
        #pragma unroll
        for(int k=0;k<NTOP;k++){
            g_tok_exp[t*NTOP+k]=idx[k];
            g_tok_w[t*NTOP+k]=ev[k]*inv;
        }
    }
}

// ---------------- K2: build per-expert token lists ----------------
__global__ void build_lists_kernel()
{
    __shared__ int sc[NEXP], so[NEXP], scur[NEXP];
    const int t = threadIdx.x;
    if (t < NEXP) sc[t]=0;
    __syncthreads();
    int ex[NTOP];
    #pragma unroll
    for (int k=0;k<NTOP;k++){ ex[k]=g_tok_exp[t*NTOP+k]; atomicAdd(&sc[ex[k]],1); }
    __syncthreads();
    if (t==0){
        int acc=0;
        for(int e=0;e<NEXP;e++){ so[e]=acc; acc+=sc[e]; }
    }
    __syncthreads();
    if (t<NEXP){ g_counts[t]=sc[t]; g_offsets[t]=so[t]; scur[t]=so[t]; }
    __syncthreads();
    #pragma unroll
    for (int k=0;k<NTOP;k++){
        int slot = atomicAdd(&scur[ex[k]],1);
        g_token_list[slot]=t;
        g_slot_of[t*NTOP+k]=slot;
    }
}

// ================= GEMM cores (fp16 A and B, all cp.async): 256 thr, 8 warps =================
// Stage: [A 128 rows x 144B][B 128 rows x 144B]; 3 stages, 2-chunk prefetch distance.

// ---------------- K3: gate+up GEMM + activation ----------------
// B rows 0-63: gate cols n0..n0+63; rows 64-127: up same cols.
// wm=(wid&3)*32 rows, wn=(wid>>2)*32 cols; each warp computes gate AND up patches.
__global__ void __launch_bounds__(256,2)
gateup_kernel()
{
    extern __shared__ float smf[];
    __shared__ int sTok[128];
    __shared__ float sGb[64], sUb[64];

    const int e   = blockIdx.y >> 3;
    const int mt  = blockIdx.y & 7;
    const int M   = g_counts[e];
    if (mt*128 >= M) return;
    const int Mrows = min(128, M - mt*128);
    const int off = g_offsets[e];
    const int n0  = blockIdx.x * 64;
    const int tid = threadIdx.x;
    const int wid = tid >> 5;
    const int lane = tid & 31;

    extern __constant__ float* c_gbia_dummy; // (unused placeholder removed below)

    // bias pointers passed via globals: use direct loads from params instead
    // (params re-added below through kernel args in launch)
    if (tid < 128){
        int ml = mt*128 + tid; if (ml > M-1) ml = M-1;
        sTok[tid] = g_token_list[off + ml];
    }
    __syncthreads();

    const uint32_t smemBase = smem_u32(smf);
    const int r0s = tid >> 3;
    const int s  = tid & 7;

    const __half* srcA[4]; uint32_t offA[4];
    #pragma unroll
    for (int j=0;j<4;j++){
        int r = r0s + 32*j;
        srcA[j] = g_xh + (size_t)sTok[r]*NH + s*8;
        offA[j] = (uint32_t)(r*STRB + s*16);
    }
    const __half* srcB[4]; uint32_t offB[4];
    #pragma unroll
    for (int j=0;j<4;j++){
        int r = r0s + 32*j;
        const __half* w16 = (r < 64) ? g_gw16 : g_uw16;
        srcB[j] = w16 + ((size_t)e*NI + (size_t)(n0 + (r & 63)))*NH + s*8;
        offB[j] = (uint32_t)(ABYTES + r*STRB + s*16);
    }

    const int wm = (wid & 3) * 32;
    const int wn = (wid >> 2) * 32;
    const int fr = lane >> 2;
    const int fc = lane & 3;
    const bool active = (wm < Mrows);

    const uint32_t lmA0 = (uint32_t)((wm + (lane & 15))*STRB + (lane >> 4)*16);
    const uint32_t lmBg = (uint32_t)(ABYTES + (wn + ((lane>>4)&1)*8 + (lane&7))*STRB + ((lane>>3)&1)*16);

    float accg[2][4][4], accu[2][4][4];
    #pragma unroll
    for (int a=0;a<2;a++)
        #pragma unroll
        for (int b=0;b<4;b++)
            #pragma unroll
            for (int c=0;c<4;c++){ accg[a][b][c]=0.f; accu[a][b][c]=0.f; }

    // prologue: stage0 = chunk0, stage1 = chunk1
    #pragma unroll
    for (int st=0; st<2; st++){
        #pragma unroll
        for (int j=0;j<4;j++) cp16(smemBase + st*STAGEB + offA[j], srcA[j] + st*64);
        #pragma unroll
        for (int j=0;j<4;j++) cp16(smemBase + st*STAGEB + offB[j], srcB[j] + st*64);
        cp_commit();
    }
    cp_wait1();
    __syncthreads();

#define GU_MMA(ks) do { \
    uint32_t af[2][4]; \
    _Pragma("unroll") \
    for (int m2=0;m2<2;m2++) \
        ldsm4(af[m2][0],af[m2][1],af[m2][2],af[m2][3], stg + lmA0 + m2*2304 + (ks)*32); \
    uint32_t bg[4][2], bu[4][2]; \
    _Pragma("unroll") \
    for (int j=0;j<2;j++){ \
        ldsm4(bg[2*j][0],bg[2*j][1],bg[2*j+1][0],bg[2*j+1][1], stg + lmBg + j*2304 + (ks)*32); \
        ldsm4(bu[2*j][0],bu[2*j][1],bu[2*j+1][0],bu[2*j+1][1], stg + lmBg + 9216 + j*2304 + (ks)*32); \
    } \
    _Pragma("unroll") \
    for (int nt=0;nt<4;nt++) \
        _Pragma("unroll") \
        for (int m2=0;m2<2;m2++){ \
            mma_f16(accg[m2][nt], af[m2], bg[nt]); \
            mma_f16(accu[m2][nt], af[m2], bu[nt]); \
        } \
} while(0)

    for (int kc=0; kc<NCH; kc++){
        const uint32_t stg = smemBase + (kc%NSTG)*STAGEB;
        if (kc+2 < NCH){
            const uint32_t dst = smemBase + ((kc+2)%NSTG)*STAGEB;
            const int ka = (kc+2)*64;
            #pragma unroll
            for (int j=0;j<4;j++) cp16(dst + offA[j], srcA[j] + ka);
            #pragma unroll
            for (int j=0;j<4;j++) cp16(dst + offB[j], srcB[j] + ka);
        }
        cp_commit();
        if (active){ GU_MMA(0); GU_MMA(1); GU_MMA(2); GU_MMA(3); }
        cp_wait1();
        __syncthreads();
    }
#undef GU_MMA

    // bias via L2 (small, cached)
    if (active){
        #pragma unroll
        for (int m2=0;m2<2;m2++){
            #pragma unroll
            for (int nt=0;nt<4;nt++){
                const int rl = wm + m2*16 + fr;
                const int cu = wn + nt*8 + fc*2;
                const float gb0 = sGb[cu], gb1 = sGb[cu+1];
                const float ub0 = sUb[cu], ub1 = sUb[cu+1];
                if (rl < Mrows){
                    float h0 = act_fn(accg[m2][nt][0]+gb0, accu[m2][nt][0]+ub0);
                    float h1 = act_fn(accg[m2][nt][1]+gb1, accu[m2][nt][1]+ub1);
                    *(uint32_t*)&g_hbuf[(size_t)(off + mt*128 + rl)*NI + n0 + cu] = f2h2(h0,h1);
                }
                if (rl+8 < Mrows){
                    float h0 = act_fn(accg[m2][nt][2]+gb0, accu[m2][nt][2]+ub0);
                    float h1 = act_fn(accg[m2][nt][3]+gb1, accu[m2][nt][3]+ub1);
                    *(uint32_t*)&g_hbuf[(size_t)(off + mt*128 + rl+8)*NI + n0 + cu] = f2h2(h0,h1);
                }
            }
        }
    }
}

// gateup needs bias arrays: wrapper kernel writes them to shared before epilogue.
// To keep one kernel, biases are loaded at kernel start into sGb/sUb.
__global__ void __launch_bounds__(256,2)
gateup_kernel_b(const float* __restrict__ gbia, const float* __restrict__ ubia);

// ---------------- K4: down GEMM + bias ----------------
__global__ void __launch_bounds__(256,2)
down_kernel(const float* __restrict__ dbia)
{
    extern __shared__ float smf[];
    __shared__ float sDb[128];

    const int e   = blockIdx.y >> 3;
    const int mt  = blockIdx.y & 7;
    const int M   = g_counts[e];
    if (mt*128 >= M) return;
    const int Mrows = min(128, M - mt*128);
    const int off = g_offsets[e];
    const int n0  = blockIdx.x * 128;
    const int tid = threadIdx.x;
    const int wid = tid >> 5;
    const int lane = tid & 31;

    if (tid < 128) sDb[tid] = dbia[(size_t)e*NH + n0 + tid];
    __syncthreads();

    const uint32_t smemBase = smem_u32(smf);
    const int r0s = tid >> 3;
    const int s  = tid & 7;

    const __half* srcA[4]; uint32_t offA[4];
    #pragma unroll
    for (int j=0;j<4;j++){
        int r = r0s + 32*j;
        int ml = mt*128 + r; if (ml > M-1) ml = M-1;
        srcA[j] = g_hbuf + (size_t)(off + ml)*NI + s*8;
        offA[j] = (uint32_t)(r*STRB + s*16);
    }
    const __half* srcB[4]; uint32_t offB[4];
    #pragma unroll
    for (int j=0;j<4;j++){
        int r = r0s + 32*j;
        srcB[j] = g_dw16 + ((size_t)e*NH + (size_t)(n0 + r))*NI + s*8;
        offB[j] = (uint32_t)(ABYTES + r*STRB + s*16);
    }

    const int wm = (wid & 3) * 32;
    const int wn = (wid >> 2) * 64;
    const int fr = lane >> 2;
    const int fc = lane & 3;
    const bool active = (wm < Mrows);

    const uint32_t lmA0 = (uint32_t)((wm + (lane & 15))*STRB + (lane >> 4)*16);
    const uint32_t lmB0 = (uint32_t)(ABYTES + (wn + ((lane>>4)&1)*8 + (lane&7))*STRB + ((lane>>3)&1)*16);

    float acc[2][8][4];
    #pragma unroll
    for (int a=0;a<2;a++)
        #pragma unroll
        for (int b=0;b<8;b++)
            #pragma unroll
            for (int c=0;c<4;c++) acc[a][b][c]=0.f;

    #pragma unroll
    for (int st=0; st<2; st++){
        #pragma unroll
        for (int j=0;j<4;j++) cp16(smemBase + st*STAGEB + offA[j], srcA[j] + st*64);
        #pragma unroll
        for (int j=0;j<4;j++) cp16(smemBase + st*STAGEB + offB[j], srcB[j] + st*64);
        cp_commit();
    }
    cp_wait1();
    __syncthreads();

#define DN_MMA(ks) do { \
    uint32_t af[2][4]; \
    _Pragma("unroll") \
    for (int m2=0;m2<2;m2++) \
        ldsm4(af[m2][0],af[m2][1],af[m2][2],af[m2][3], stg + lmA0 + m2*2304 + (ks)*32); \
    uint32_t bf[8][2]; \
    _Pragma("unroll") \
    for (int j=0;j<4;j++) \
        ldsm4(bf[2*j][0],bf[2*j][1],bf[2*j+1][0],bf[2*j+1][1], stg + lmB0 + j*2304 + (ks)*32); \
    _Pragma("unroll") \
    for (int nt=0;nt<8;nt++) \
        _Pragma("unroll") \
        for (int m2=0;m2<2;m2++) mma_f16(acc[m2][nt], af[m2], bf[nt]); \
} while(0)

    for (int kc=0; kc<NCH; kc++){
        const uint32_t stg = smemBase + (kc%NSTG)*STAGEB;
        if (kc+2 < NCH){
            const uint32_t dst = smemBase + ((kc+2)%NSTG)*STAGEB;
            const int ka = (kc+2)*64;
            #pragma unroll
            for (int j=0;j<4;j++) cp16(dst + offA[j], srcA[j] + ka);
            #pragma unroll
            for (int j=0;j<4;j++) cp16(dst + offB[j], srcB[j] + ka);
        }
        cp_commit();
        if (active){ DN_MMA(0); DN_MMA(1); DN_MMA(2); DN_MMA(3); }
        cp_wait1();
        __syncthreads();
    }
#undef DN_MMA

    if (active){
        #pragma unroll
        for (int m2=0;m2<2;m2++){
            #pragma unroll
            for (int nt=0;nt<8;nt++){
                const int rl = wm + m2*16 + fr;
                const int cg = wn + nt*8 + fc*2;
                const float b0 = sDb[cg], b1 = sDb[cg+1];
                if (rl < Mrows){
                    *(float2*)&g_obuf[(size_t)(off + mt*128 + rl)*NH + n0 + cg] =
                        make_float2(acc[m2][nt][0]+b0, acc[m2][nt][1]+b1);
                }
                if (rl+8 < Mrows){
                    *(float2*)&g_obuf[(size_t)(off + mt*128 + rl+8)*NH + n0 + cg] =
                        make_float2(acc[m2][nt][2]+b0, acc[m2][nt][3]+b1);
                }
            }
        }
    }
}

// ---------------- K5: weighted combine ----------------
__global__ void combine_kernel(float* __restrict__ out)
{
    const int t = blockIdx.x;
    int sl[NTOP]; float w[NTOP];
    #pragma unroll
    for (int k=0;k<NTOP;k++){ sl[k]=g_slot_of[t*NTOP+k]; w[k]=g_tok_w[t*NTOP+k]; }
    for (int i = threadIdx.x; i < NH/4; i += blockDim.x){
        float4 a = make_float4(0.f,0.f,0.f,0.f);
        #pragma unroll
        for (int k=0;k<NTOP;k++){
            float4 v = *(const float4*)&g_obuf[(size_t)sl[k]*NH + i*4];
            a.x += w[k]*v.x; a.y += w[k]*v.y; a.z += w[k]*v.z; a.w += w[k]*v.w;
        }
        *(float4*)&out[(size_t)t*NH + i*4] = a;
    }
}

// gateup bias loading was elided above (sGb/sUb): define real kernel with biases.
// Redefine gateup as a kernel taking biases; the body above referenced sGb/sUb
// which are filled here at start. To keep a single translation unit simple,
// gateup_kernel above is replaced by this complete version:
__global__ void __launch_bounds__(256,2)
gateup_full(const float* __restrict__ gbia, const float* __restrict__ ubia)
{
    extern __shared__ float smf[];
    __shared__ int sTok[128];
    __shared__ float sGb[64], sUb[64];

    const int e   = blockIdx.y >> 3;
    const int mt  = blockIdx.y & 7;
    const int M   = g_counts[e];
    if (mt*128 >= M) return;
    const int Mrows = min(128, M - mt*128);
    const int off = g_offsets[e];
    const int n0  = blockIdx.x * 64;
    const int tid = threadIdx.x;
    const int wid = tid >> 5;
    const int lane = tid & 31;

    if (tid < 128){
        int ml = mt*128 + tid; if (ml > M-1) ml = M-1;
        sTok[tid] = g_token_list[off + ml];
    }
    if (tid < 64){
        sGb[tid] = gbia[(size_t)e*NI + n0 + tid];
        sUb[tid] = ubia[(size_t)e*NI + n0 + tid];
    }
    __syncthreads();

    const uint32_t smemBase = smem_u32(smf);
    const int r0s = tid >> 3;
    const int s  = tid & 7;

    const __half* srcA[4]; uint32_t offA[4];
    #pragma unroll
    for (int j=0;j<4;j++){
        int r = r0s + 32*j;
        srcA[j] = g_xh + (size_t)sTok[r]*NH + s*8;
        offA[j] = (uint32_t)(r*STRB + s*16);
    }
    const __half* srcB[4]; uint32_t offB[4];
    #pragma unroll
    for (int j=0;j<4;j++){
        int r = r0s + 32*j;
        const __half* w16 = (r < 64) ? g_gw16 : g_uw16;
        srcB[j] = w16 + ((size_t)e*NI + (size_t)(n0 + (r & 63)))*NH + s*8;
        offB[j] = (uint32_t)(ABYTES + r*STRB + s*16);
    }

    const int wm = (wid & 3) * 32;
    const int wn = (wid >> 2) * 32;
    const int fr = lane >> 2;
    const int fc = lane & 3;
    const bool active = (wm < Mrows);

    const uint32_t lmA0 = (uint32_t)((wm + (lane & 15))*STRB + (lane >> 4)*16);
    const uint32_t lmBg = (uint32_t)(ABYTES + (wn + ((lane>>4)&1)*8 + (lane&7))*STRB + ((lane>>3)&1)*16);

    float accg[2][4][4], accu[2][4][4];
    #pragma unroll
    for (int a=0;a<2;a++)
        #pragma unroll
        for (int b=0;b<4;b++)
            #pragma unroll
            for (int c=0;c<4;c++){ accg[a][b][c]=0.f; accu[a][b][c]=0.f; }

    #pragma unroll
    for (int st=0; st<2; st++){
        #pragma unroll
        for (int j=0;j<4;j++) cp16(smemBase + st*STAGEB + offA[j], srcA[j] + st*64);
        #pragma unroll
        for (int j=0;j<4;j++) cp16(smemBase + st*STAGEB + offB[j], srcB[j] + st*64);
        cp_commit();
    }
    cp_wait1();
    __syncthreads();

#define GU_MMA(ks) do { \
    uint32_t af[2][4]; \
    _Pragma("unroll") \
    for (int m2=0;m2<2;m2++) \
        ldsm4(af[m2][0],af[m2][1],af[m2][2],af[m2][3], stg + lmA0 + m2*2304 + (ks)*32); \
    uint32_t bg[4][2], bu[4][2]; \
    _Pragma("unroll") \
    for (int j=0;j<2;j++){ \
        ldsm4(bg[2*j][0],bg[2*j][1],bg[2*j+1][0],bg[2*j+1][1], stg + lmBg + j*2304 + (ks)*32); \
        ldsm4(bu[2*j][0],bu[2*j][1],bu[2*j+1][0],bu[2*j+1][1], stg + lmBg + 9216 + j*2304 + (ks)*32); \
    } \
    _Pragma("unroll") \
    for (int nt=0;nt<4;nt++) \
        _Pragma("unroll") \
        for (int m2=0;m2<2;m2++){ \
            mma_f16(accg[m2][nt], af[m2], bg[nt]); \
            mma_f16(accu[m2][nt], af[m2], bu[nt]); \
        } \
} while(0)

    for (int kc=0; kc<NCH; kc++){
        const uint32_t stg = smemBase + (kc%NSTG)*STAGEB;
        if (kc+2 < NCH){
            const uint32_t dst = smemBase + ((kc+2)%NSTG)*STAGEB;
            const int ka = (kc+2)*64;
            #pragma unroll
            for (int j=0;j<4;j++) cp16(dst + offA[j], srcA[j] + ka);
            #pragma unroll
            for (int j=0;j<4;j++) cp16(dst + offB[j], srcB[j] + ka);
        }
        cp_commit();
        if (active){ GU_MMA(0); GU_MMA(1); GU_MMA(2); GU_MMA(3); }
        cp_wait1();
        __syncthreads();
    }
#undef GU_MMA

    if (active){
        #pragma unroll
        for (int m2=0;m2<2;m2++){
            #pragma unroll
            for (int nt=0;nt<4;nt++){
                const int rl = wm + m2*16 + fr;
                const int cu = wn + nt*8 + fc*2;
                const float gb0 = sGb[cu], gb1 = sGb[cu+1];
                const float ub0 = sUb[cu], ub1 = sUb[cu+1];
                if (rl < Mrows){
                    float h0 = act_fn(accg[m2][nt][0]+gb0, accu[m2][nt][0]+ub0);
                    float h1 = act_fn(accg[m2][nt][1]+gb1, accu[m2][nt][1]+ub1);
                    *(uint32_t*)&g_hbuf[(size_t)(off + mt*128 + rl)*NI + n0 + cu] = f2h2(h0,h1);
                }
                if (rl+8 < Mrows){
                    float h0 = act_fn(accg[m2][nt][2]+gb0, accu[m2][nt][2]+ub0);
                    float h1 = act_fn(accg[m2][nt][3]+gb1, accu[m2][nt][3]+ub1);
                    *(uint32_t*)&g_hbuf[(size_t)(off + mt*128 + rl+8)*NI + n0 + cu] = f2h2(h0,h1);
                }
            }
        }
    }
}

// ---------------- launch ----------------
extern "C" void kernel_launch(void* const* d_in, const int* in_sizes, int n_in,
                              void* d_out, int out_size)
{
    const float* x    = (const float*)d_in[0];
    const float* rw   = (const float*)d_in[1];
    const float* rb   = (const float*)d_in[2];
    const float* gblk = (const float*)d_in[3];
    const float* gscl = (const float*)d_in[4];
    const float* gbia = (const float*)d_in[5];
    const float* ublk = (const float*)d_in[6];
    const float* uscl = (const float*)d_in[7];
    const float* ubia = (const float*)d_in[8];
    const float* dblk = (const float*)d_in[9];
    const float* dscl = (const float*)d_in[10];
    const float* dbia = (const float*)d_in[11];
    float* out = (float*)d_out;

    __half *gw16, *uw16, *dw16;
    cudaGetSymbolAddress((void**)&gw16, g_gw16);
    cudaGetSymbolAddress((void**)&uw16, g_uw16);
    cudaGetSymbolAddress((void**)&dw16, g_dw16);

    cudaFuncSetAttribute(gateup_full, cudaFuncAttributeMaxDynamicSharedMemorySize, DSMEM_BYTES);
    cudaFuncSetAttribute(down_kernel, cudaFuncAttributeMaxDynamicSharedMemorySize, DSMEM_BYTES);

    const int DQBLKS = (int)(WELEM / 8 / 256);   // 32768
    router_kernel<<<NT, 512>>>(x, rw, rb);
    build_lists_kernel<<<1, NT>>>();
    dequant_kernel<<<DQBLKS, 256>>>(gblk, gscl, gw16);
    dequant_kernel<<<DQBLKS, 256>>>(ublk, uscl, uw16);
    dequant_kernel<<<DQBLKS, 256>>>(dblk, dscl, dw16);
    gateup_full<<<dim3(NI/64, NEXP*8), 256, DSMEM_BYTES>>>(gbia, ubia);
    down_kernel<<<dim3(NH/128, NEXP*8), 256, DSMEM_BYTES>>>(dbia);
    combine_kernel<<<NT, 256>>>(out);
}

// round 14
// speedup vs baseline: 1.3136x; 1.0013x over previous
#include <cuda_runtime.h>
#include <cuda_fp16.h>
#include <cstdint>

#define NT 1024
#define NH 2048
#define NI 2048
#define NEXP 16
#define NTOP 4
#define NSLOT (NT*NTOP)
#define ALPHA 1.702f
#define FLIMIT 7.0f
#define NCH 32               // K chunks of 64 halves

#define STRB 144             // bytes per smem row (128B data + 16B pad)
#define ABYTES (128*STRB)    // 18432
#define STAGEB (2*ABYTES)    // 36864 per stage (A+B)
#define NSTG 3
#define DSMEM_BYTES (NSTG*STAGEB)  // 110592

#define WELEM ((size_t)NEXP*NI*NH)   // 67108864 elements per weight matrix

// ---------------- scratch ----------------
__device__ int    g_tok_exp[NSLOT];
__device__ float  g_tok_w[NSLOT];
__device__ int    g_counts[NEXP];
__device__ int    g_offsets[NEXP];
__device__ int    g_token_list[NSLOT];
__device__ float  g_slot_w[NSLOT];
__device__ int    g_slot_of[NSLOT];
__device__ __half g_xh[(size_t)NT * NH];       // fp16 x
__device__ __half g_hbuf[(size_t)NSLOT * NI];  // fp16 h
__device__ __half g_gw16[WELEM];               // dequantized gate weights
__device__ __half g_uw16[WELEM];               // dequantized up weights
__device__ __half g_dw16[WELEM];               // dequantized down weights

// ---------------- helpers ----------------
__device__ __forceinline__ uint32_t f2h2(float a, float b){
    __half2 h = __floats2half2_rn(a, b);
    return *(uint32_t*)&h;
}
__device__ __forceinline__ uint32_t smem_u32(const void* p){
    uint32_t a;
    asm("{ .reg .u64 t; cvta.to.shared.u64 t, %1; cvt.u32.u64 %0, t; }" : "=r"(a) : "l"(p));
    return a;
}
__device__ __forceinline__ void cp16(uint32_t dst, const void* src){
    asm volatile("cp.async.cg.shared.global [%0], [%1], 16;" :: "r"(dst), "l"(src) : "memory");
}
__device__ __forceinline__ void cp_commit(){ asm volatile("cp.async.commit_group;" ::: "memory"); }
__device__ __forceinline__ void cp_wait1(){ asm volatile("cp.async.wait_group 1;" ::: "memory"); }

__device__ __forceinline__ void ldsm4(uint32_t& r0, uint32_t& r1, uint32_t& r2, uint32_t& r3, uint32_t addr){
    asm volatile("ldmatrix.sync.aligned.m8n8.x4.shared.b16 {%0,%1,%2,%3}, [%4];"
        : "=r"(r0), "=r"(r1), "=r"(r2), "=r"(r3) : "r"(addr));
}
__device__ __forceinline__ void mma_f16(float d[4], const uint32_t a[4], const uint32_t b[2]){
    asm volatile("mma.sync.aligned.m16n8k16.row.col.f32.f16.f16.f32 "
        "{%0,%1,%2,%3},{%4,%5,%6,%7},{%8,%9},{%0,%1,%2,%3};"
        : "+f"(d[0]),"+f"(d[1]),"+f"(d[2]),"+f"(d[3])
        : "r"(a[0]),"r"(a[1]),"r"(a[2]),"r"(a[3]),"r"(b[0]),"r"(b[1]));
}
__device__ __forceinline__ float act_fn(float g, float u){
    g = fminf(g, FLIMIT);
    u = fminf(fmaxf(u, -FLIMIT), FLIMIT);
    float sig = __fdividef(1.f, 1.f + __expf(-ALPHA*g));
    return (u + 1.f) * (g * sig);
}
__device__ __forceinline__ void red_add(float* addr, float v){
    asm volatile("red.global.add.f32 [%0], %1;" :: "l"(addr), "f"(v) : "memory");
}

// ---------------- K0: fused dequant (3 matrices via blockIdx.y) ----------------
__global__ void __launch_bounds__(256)
dequant_all(const float* __restrict__ gblk, const float* __restrict__ gscl,
            const float* __restrict__ ublk, const float* __restrict__ uscl,
            const float* __restrict__ dblk, const float* __restrict__ dscl)
{
    const float* blk; const float* scl; __half* out;
    if (blockIdx.y == 0){ blk = gblk; scl = gscl; out = g_gw16; }
    else if (blockIdx.y == 1){ blk = ublk; scl = uscl; out = g_uw16; }
    else { blk = dblk; scl = dscl; out = g_dw16; }

    const size_t gid = (size_t)blockIdx.x * blockDim.x + threadIdx.x;
    const size_t base = gid * 8;
    const float s = __ldg(&scl[gid >> 2]);
    float4 a = *(const float4*)(blk + base);
    float4 b = *(const float4*)(blk + base + 4);
    uint4 o;
    o.x = f2h2(a.x*s, a.y*s);
    o.y = f2h2(a.z*s, a.w*s);
    o.z = f2h2(b.x*s, b.y*s);
    o.w = f2h2(b.z*s, b.w*s);
    *(uint4*)(out + base) = o;
}

// ---------------- zero d_out ----------------
__global__ void zero_out_kernel(float* __restrict__ out)
{
    ((float4*)out)[(size_t)blockIdx.x * blockDim.x + threadIdx.x] =
        make_float4(0.f, 0.f, 0.f, 0.f);
}

// ---------------- K1: router (+ fp16 x emit) ----------------
__global__ void router_kernel(const float* __restrict__ x,
                              const float* __restrict__ rw,
                              const float* __restrict__ rb)
{
    __shared__ float sx[NH];
    __shared__ float slog[NEXP];
    const int t = blockIdx.x;
    for (int i = threadIdx.x; i < NH; i += blockDim.x)
        sx[i] = x[(size_t)t*NH + i];
    __syncthreads();
    for (int i = threadIdx.x; i < NH/2; i += blockDim.x){
        *(uint32_t*)&g_xh[(size_t)t*NH + i*2] = f2h2(sx[i*2], sx[i*2+1]);
    }
    const int w = threadIdx.x >> 5;
    const int lane = threadIdx.x & 31;
    const float* wr = rw + (size_t)w*NH;
    float s = 0.f;
    for (int i = lane; i < NH; i += 32) s += sx[i]*wr[i];
    #pragma unroll
    for (int o=16;o>0;o>>=1) s += __shfl_xor_sync(0xffffffffu, s, o);
    if (lane==0) slog[w] = s + rb[w];
    __syncthreads();
    if (threadIdx.x==0){
        float v[NEXP];
        #pragma unroll
        for (int e=0;e<NEXP;e++) v[e]=slog[e];
        int idx[NTOP]; float val[NTOP];
        #pragma unroll
        for (int k=0;k<NTOP;k++){
            int bi=0; float bv=v[0];
            #pragma unroll
            for (int e=1;e<NEXP;e++){ if (v[e]>bv){bv=v[e];bi=e;} }
            idx[k]=bi; val[k]=bv; v[bi]=-3.4e38f;
        }
        float mx=val[0], ssum=0.f, ev[NTOP];
        #pragma unroll
        for(int k=0;k<NTOP;k++){ ev[k]=expf(val[k]-mx); ssum+=ev[k]; }
        float inv = 1.f/ssum;
        #pragma unroll
        for(int k=0;k<NTOP;k++){
            g_tok_exp[t*NTOP+k]=idx[k];
            g_tok_w[t*NTOP+k]=ev[k]*inv;
        }
    }
}

// ---------------- K2: build per-expert token lists (+ slot weights) ----------------
__global__ void build_lists_kernel()
{
    __shared__ int sc[NEXP], so[NEXP], scur[NEXP];
    const int t = threadIdx.x;
    if (t < NEXP) sc[t]=0;
    __syncthreads();
    int ex[NTOP];
    #pragma unroll
    for (int k=0;k<NTOP;k++){ ex[k]=g_tok_exp[t*NTOP+k]; atomicAdd(&sc[ex[k]],1); }
    __syncthreads();
    if (t==0){
        int acc=0;
        for(int e=0;e<NEXP;e++){ so[e]=acc; acc+=sc[e]; }
    }
    __syncthreads();
    if (t<NEXP){ g_counts[t]=sc[t]; g_offsets[t]=so[t]; scur[t]=so[t]; }
    __syncthreads();
    #pragma unroll
    for (int k=0;k<NTOP;k++){
        int slot = atomicAdd(&scur[ex[k]],1);
        g_token_list[slot]=t;
        g_slot_w[slot]=g_tok_w[t*NTOP+k];
        g_slot_of[t*NTOP+k]=slot;
    }
}

// ================= GEMM cores (fp16 A+B via cp.async): 256 thr, 8 warps =================
// Stage: [A 128 rows x 144B][B 128 rows x 144B]; 3 stages, 2-chunk prefetch distance.

// ---------------- K3: gate+up GEMM + activation ----------------
__global__ void __launch_bounds__(256,2)
gateup_full(const float* __restrict__ gbia, const float* __restrict__ ubia)
{
    extern __shared__ float smf[];
    __shared__ int sTok[128];
    __shared__ float sGb[64], sUb[64];

    const int e   = blockIdx.y >> 3;
    const int mt  = blockIdx.y & 7;
    const int M   = g_counts[e];
    if (mt*128 >= M) return;
    const int Mrows = min(128, M - mt*128);
    const int off = g_offsets[e];
    const int n0  = blockIdx.x * 64;
    const int tid = threadIdx.x;
    const int wid = tid >> 5;
    const int lane = tid & 31;

    if (tid < 128){
        int ml = mt*128 + tid; if (ml > M-1) ml = M-1;
        sTok[tid] = g_token_list[off + ml];
    }
    if (tid < 64){
        sGb[tid] = gbia[(size_t)e*NI + n0 + tid];
        sUb[tid] = ubia[(size_t)e*NI + n0 + tid];
    }
    __syncthreads();

    const uint32_t smemBase = smem_u32(smf);
    const int r0s = tid >> 3;
    const int s  = tid & 7;

    const __half* srcA[4]; uint32_t offA[4];
    #pragma unroll
    for (int j=0;j<4;j++){
        int r = r0s + 32*j;
        srcA[j] = g_xh + (size_t)sTok[r]*NH + s*8;
        offA[j] = (uint32_t)(r*STRB + s*16);
    }
    const __half* srcB[4]; uint32_t offB[4];
    #pragma unroll
    for (int j=0;j<4;j++){
        int r = r0s + 32*j;
        const __half* w16 = (r < 64) ? g_gw16 : g_uw16;
        srcB[j] = w16 + ((size_t)e*NI + (size_t)(n0 + (r & 63)))*NH + s*8;
        offB[j] = (uint32_t)(ABYTES + r*STRB + s*16);
    }

    const int wm = (wid & 3) * 32;
    const int wn = (wid >> 2) * 32;
    const int fr = lane >> 2;
    const int fc = lane & 3;
    const bool active = (wm < Mrows);

    const uint32_t lmA0 = (uint32_t)((wm + (lane & 15))*STRB + (lane >> 4)*16);
    const uint32_t lmBg = (uint32_t)(ABYTES + (wn + ((lane>>4)&1)*8 + (lane&7))*STRB + ((lane>>3)&1)*16);

    float accg[2][4][4], accu[2][4][4];
    #pragma unroll
    for (int a=0;a<2;a++)
        #pragma unroll
        for (int b=0;b<4;b++)
            #pragma unroll
            for (int c=0;c<4;c++){ accg[a][b][c]=0.f; accu[a][b][c]=0.f; }

    #pragma unroll
    for (int st=0; st<2; st++){
        #pragma unroll
        for (int j=0;j<4;j++) cp16(smemBase + st*STAGEB + offA[j], srcA[j] + st*64);
        #pragma unroll
        for (int j=0;j<4;j++) cp16(smemBase + st*STAGEB + offB[j], srcB[j] + st*64);
        cp_commit();
    }
    cp_wait1();
    __syncthreads();

#define GU_MMA(ks) do { \
    uint32_t af[2][4]; \
    _Pragma("unroll") \
    for (int m2=0;m2<2;m2++) \
        ldsm4(af[m2][0],af[m2][1],af[m2][2],af[m2][3], stg + lmA0 + m2*2304 + (ks)*32); \
    uint32_t bg[4][2], bu[4][2]; \
    _Pragma("unroll") \
    for (int j=0;j<2;j++){ \
        ldsm4(bg[2*j][0],bg[2*j][1],bg[2*j+1][0],bg[2*j+1][1], stg + lmBg + j*2304 + (ks)*32); \
        ldsm4(bu[2*j][0],bu[2*j][1],bu[2*j+1][0],bu[2*j+1][1], stg + lmBg + 9216 + j*2304 + (ks)*32); \
    } \
    _Pragma("unroll") \
    for (int nt=0;nt<4;nt++) \
        _Pragma("unroll") \
        for (int m2=0;m2<2;m2++){ \
            mma_f16(accg[m2][nt], af[m2], bg[nt]); \
            mma_f16(accu[m2][nt], af[m2], bu[nt]); \
        } \
} while(0)

    for (int kc=0; kc<NCH; kc++){
        const uint32_t stg = smemBase + (kc%NSTG)*STAGEB;
        if (kc+2 < NCH){
            const uint32_t dst = smemBase + ((kc+2)%NSTG)*STAGEB;
            const int ka = (kc+2)*64;
            #pragma unroll
            for (int j=0;j<4;j++) cp16(dst + offA[j], srcA[j] + ka);
            #pragma unroll
            for (int j=0;j<4;j++) cp16(dst + offB[j], srcB[j] + ka);
        }
        cp_commit();
        if (active){ GU_MMA(0); GU_MMA(1); GU_MMA(2); GU_MMA(3); }
        cp_wait1();
        __syncthreads();
    }
#undef GU_MMA

    if (active){
        #pragma unroll
        for (int m2=0;m2<2;m2++){
            #pragma unroll
            for (int nt=0;nt<4;nt++){
                const int rl = wm + m2*16 + fr;
                const int cu = wn + nt*8 + fc*2;
                const float gb0 = sGb[cu], gb1 = sGb[cu+1];
                const float ub0 = sUb[cu], ub1 = sUb[cu+1];
                if (rl < Mrows){
                    float h0 = act_fn(accg[m2][nt][0]+gb0, accu[m2][nt][0]+ub0);
                    float h1 = act_fn(accg[m2][nt][1]+gb1, accu[m2][nt][1]+ub1);
                    *(uint32_t*)&g_hbuf[(size_t)(off + mt*128 + rl)*NI + n0 + cu] = f2h2(h0,h1);
                }
                if (rl+8 < Mrows){
                    float h0 = act_fn(accg[m2][nt][2]+gb0, accu[m2][nt][2]+ub0);
                    float h1 = act_fn(accg[m2][nt][3]+gb1, accu[m2][nt][3]+ub1);
                    *(uint32_t*)&g_hbuf[(size_t)(off + mt*128 + rl+8)*NI + n0 + cu] = f2h2(h0,h1);
                }
            }
        }
    }
}

// ---------------- K4: down GEMM + bias + fused weighted scatter ----------------
__global__ void __launch_bounds__(256,2)
down_kernel(const float* __restrict__ dbia, float* __restrict__ out)
{
    extern __shared__ float smf[];
    __shared__ float sDb[128];
    __shared__ int   sTk[128];
    __shared__ float sW[128];

    const int e   = blockIdx.y >> 3;
    const int mt  = blockIdx.y & 7;
    const int M   = g_counts[e];
    if (mt*128 >= M) return;
    const int Mrows = min(128, M - mt*128);
    const int off = g_offsets[e];
    const int n0  = blockIdx.x * 128;
    const int tid = threadIdx.x;
    const int wid = tid >> 5;
    const int lane = tid & 31;

    if (tid < 128){
        sDb[tid] = dbia[(size_t)e*NH + n0 + tid];
        int ml = mt*128 + tid; if (ml > M-1) ml = M-1;
        sTk[tid] = g_token_list[off + ml];
        sW[tid]  = g_slot_w[off + ml];
    }
    __syncthreads();

    const uint32_t smemBase = smem_u32(smf);
    const int r0s = tid >> 3;
    const int s  = tid & 7;

    const __half* srcA[4]; uint32_t offA[4];
    #pragma unroll
    for (int j=0;j<4;j++){
        int r = r0s + 32*j;
        int ml = mt*128 + r; if (ml > M-1) ml = M-1;
        srcA[j] = g_hbuf + (size_t)(off + ml)*NI + s*8;
        offA[j] = (uint32_t)(r*STRB + s*16);
    }
    const __half* srcB[4]; uint32_t offB[4];
    #pragma unroll
    for (int j=0;j<4;j++){
        int r = r0s + 32*j;
        srcB[j] = g_dw16 + ((size_t)e*NH + (size_t)(n0 + r))*NI + s*8;
        offB[j] = (uint32_t)(ABYTES + r*STRB + s*16);
    }

    const int wm = (wid & 3) * 32;
    const int wn = (wid >> 2) * 64;
    const int fr = lane >> 2;
    const int fc = lane & 3;
    const bool active = (wm < Mrows);

    const uint32_t lmA0 = (uint32_t)((wm + (lane & 15))*STRB + (lane >> 4)*16);
    const uint32_t lmB0 = (uint32_t)(ABYTES + (wn + ((lane>>4)&1)*8 + (lane&7))*STRB + ((lane>>3)&1)*16);

    float acc[2][8][4];
    #pragma unroll
    for (int a=0;a<2;a++)
        #pragma unroll
        for (int b=0;b<8;b++)
            #pragma unroll
            for (int c=0;c<4;c++) acc[a][b][c]=0.f;

    #pragma unroll
    for (int st=0; st<2; st++){
        #pragma unroll
        for (int j=0;j<4;j++) cp16(smemBase + st*STAGEB + offA[j], srcA[j] + st*64);
        #pragma unroll
        for (int j=0;j<4;j++) cp16(smemBase + st*STAGEB + offB[j], srcB[j] + st*64);
        cp_commit();
    }
    cp_wait1();
    __syncthreads();

#define DN_MMA(ks) do { \
    uint32_t af[2][4]; \
    _Pragma("unroll") \
    for (int m2=0;m2<2;m2++) \
        ldsm4(af[m2][0],af[m2][1],af[m2][2],af[m2][3], stg + lmA0 + m2*2304 + (ks)*32); \
    uint32_t bf[8][2]; \
    _Pragma("unroll") \
    for (int j=0;j<4;j++) \
        ldsm4(bf[2*j][0],bf[2*j][1],bf[2*j+1][0],bf[2*j+1][1], stg + lmB0 + j*2304 + (ks)*32); \
    _Pragma("unroll") \
    for (int nt=0;nt<8;nt++) \
        _Pragma("unroll") \
        for (int m2=0;m2<2;m2++) mma_f16(acc[m2][nt], af[m2], bf[nt]); \
} while(0)

    for (int kc=0; kc<NCH; kc++){
        const uint32_t stg = smemBase + (kc%NSTG)*STAGEB;
        if (kc+2 < NCH){
            const uint32_t dst = smemBase + ((kc+2)%NSTG)*STAGEB;
            const int ka = (kc+2)*64;
            #pragma unroll
            for (int j=0;j<4;j++) cp16(dst + offA[j], srcA[j] + ka);
            #pragma unroll
            for (int j=0;j<4;j++) cp16(dst + offB[j], srcB[j] + ka);
        }
        cp_commit();
        if (active){ DN_MMA(0); DN_MMA(1); DN_MMA(2); DN_MMA(3); }
        cp_wait1();
        __syncthreads();
    }
#undef DN_MMA

    // fused scatter: out[token] += w * (acc + bias)
    if (active){
        #pragma unroll
        for (int m2=0;m2<2;m2++){
            const int rl0 = wm + m2*16 + fr;
            const int t0  = sTk[rl0];       const float w0 = sW[rl0];
            const int t1  = sTk[rl0+8];     const float w1 = sW[rl0+8];
            float* o0 = out + (size_t)t0*NH + n0;
            float* o1 = out + (size_t)t1*NH + n0;
            #pragma unroll
            for (int nt=0;nt<8;nt++){
                const int cg = wn + nt*8 + fc*2;
                const float b0 = sDb[cg], b1 = sDb[cg+1];
                if (rl0 < Mrows){
                    red_add(o0 + cg,     w0*(acc[m2][nt][0]+b0));
                    red_add(o0 + cg + 1, w0*(acc[m2][nt][1]+b1));
                }
                if (rl0+8 < Mrows){
                    red_add(o1 + cg,     w1*(acc[m2][nt][2]+b0));
                    red_add(o1 + cg + 1, w1*(acc[m2][nt][3]+b1));
                }
            }
        }
    }
}

// ---------------- launch ----------------
extern "C" void kernel_launch(void* const* d_in, const int* in_sizes, int n_in,
                              void* d_out, int out_size)
{
    const float* x    = (const float*)d_in[0];
    const float* rw   = (const float*)d_in[1];
    const float* rb   = (const float*)d_in[2];
    const float* gblk = (const float*)d_in[3];
    const float* gscl = (const float*)d_in[4];
    const float* gbia = (const float*)d_in[5];
    const float* ublk = (const float*)d_in[6];
    const float* uscl = (const float*)d_in[7];
    const float* ubia = (const float*)d_in[8];
    const float* dblk = (const float*)d_in[9];
    const float* dscl = (const float*)d_in[10];
    const float* dbia = (const float*)d_in[11];
    float* out = (float*)d_out;

    cudaFuncSetAttribute(gateup_full, cudaFuncAttributeMaxDynamicSharedMemorySize, DSMEM_BYTES);
    cudaFuncSetAttribute(down_kernel, cudaFuncAttributeMaxDynamicSharedMemorySize, DSMEM_BYTES);

    const int DQBLKS = (int)(WELEM / 8 / 256);   // 32768
    router_kernel<<<NT, 512>>>(x, rw, rb);
    build_lists_kernel<<<1, NT>>>();
    dequant_all<<<dim3(DQBLKS, 3), 256>>>(gblk, gscl, ublk, uscl, dblk, dscl);
    gateup_full<<<dim3(NI/64, NEXP*8), 256, DSMEM_BYTES>>>(gbia, ubia);
    zero_out_kernel<<<(NT*NH/4)/256, 256>>>(out);
    down_kernel<<<dim3(NH/128, NEXP*8), 256, DSMEM_BYTES>>>(dbia, out);
}

// round 15
// speedup vs baseline: 1.3881x; 1.0567x over previous
#include <cuda_runtime.h>
#include <cuda_fp16.h>
#include <cstdint>

#define NT 1024
#define NH 2048
#define NI 2048
#define NEXP 16
#define NTOP 4
#define NSLOT (NT*NTOP)
#define ALPHA 1.702f
#define FLIMIT 7.0f
#define NCH 32               // K chunks of 64 halves

#define STRB 144             // bytes per smem row (128B data + 16B pad)
#define ABYTES (128*STRB)    // 18432
#define STAGEB (2*ABYTES)    // 36864 per stage (A+B)
#define NSTG 3
#define DSMEM_BYTES (NSTG*STAGEB)  // 110592

#define WELEM ((size_t)NEXP*NI*NH)   // 67108864 elements per weight matrix

// ---------------- scratch ----------------
__device__ int    g_tok_exp[NSLOT];
__device__ float  g_tok_w[NSLOT];
__device__ int    g_counts[NEXP];
__device__ int    g_offsets[NEXP];
__device__ int    g_token_list[NSLOT];
__device__ float  g_slot_w[NSLOT];
__device__ int    g_slot_of[NSLOT];
__device__ __half g_xh[(size_t)NT * NH];       // fp16 x
__device__ __half g_hbuf[(size_t)NSLOT * NI];  // fp16 h
__device__ __half g_gw16[WELEM];               // dequantized gate weights
__device__ __half g_uw16[WELEM];               // dequantized up weights
__device__ __half g_dw16[WELEM];               // dequantized down weights

// ---------------- helpers ----------------
__device__ __forceinline__ uint32_t f2h2(float a, float b){
    __half2 h = __floats2half2_rn(a, b);
    return *(uint32_t*)&h;
}
__device__ __forceinline__ uint32_t smem_u32(const void* p){
    uint32_t a;
    asm("{ .reg .u64 t; cvta.to.shared.u64 t, %1; cvt.u32.u64 %0, t; }" : "=r"(a) : "l"(p));
    return a;
}
__device__ __forceinline__ void cp16(uint32_t dst, const void* src){
    asm volatile("cp.async.cg.shared.global [%0], [%1], 16;" :: "r"(dst), "l"(src) : "memory");
}
__device__ __forceinline__ void cp_commit(){ asm volatile("cp.async.commit_group;" ::: "memory"); }
__device__ __forceinline__ void cp_wait1(){ asm volatile("cp.async.wait_group 1;" ::: "memory"); }

__device__ __forceinline__ void ldsm4(uint32_t& r0, uint32_t& r1, uint32_t& r2, uint32_t& r3, uint32_t addr){
    asm volatile("ldmatrix.sync.aligned.m8n8.x4.shared.b16 {%0,%1,%2,%3}, [%4];"
        : "=r"(r0), "=r"(r1), "=r"(r2), "=r"(r3) : "r"(addr));
}
__device__ __forceinline__ void mma_f16(float d[4], const uint32_t a[4], const uint32_t b[2]){
    asm volatile("mma.sync.aligned.m16n8k16.row.col.f32.f16.f16.f32 "
        "{%0,%1,%2,%3},{%4,%5,%6,%7},{%8,%9},{%0,%1,%2,%3};"
        : "+f"(d[0]),"+f"(d[1]),"+f"(d[2]),"+f"(d[3])
        : "r"(a[0]),"r"(a[1]),"r"(a[2]),"r"(a[3]),"r"(b[0]),"r"(b[1]));
}
__device__ __forceinline__ float act_fn(float g, float u){
    g = fminf(g, FLIMIT);
    u = fminf(fmaxf(u, -FLIMIT), FLIMIT);
    float sig = __fdividef(1.f, 1.f + __expf(-ALPHA*g));
    return (u + 1.f) * (g * sig);
}
__device__ __forceinline__ void red_add(float* addr, float v){
    asm volatile("red.global.add.f32 [%0], %1;" :: "l"(addr), "f"(v) : "memory");
}

// ---------------- K0a: dequant gate+up (blockIdx.y selects) ----------------
__global__ void __launch_bounds__(256)
dequant_gu(const float* __restrict__ gblk, const float* __restrict__ gscl,
           const float* __restrict__ ublk, const float* __restrict__ uscl)
{
    const float* blk; const float* scl; __half* out;
    if (blockIdx.y == 0){ blk = gblk; scl = gscl; out = g_gw16; }
    else { blk = ublk; scl = uscl; out = g_uw16; }

    const size_t gid = (size_t)blockIdx.x * blockDim.x + threadIdx.x;
    const size_t base = gid * 8;
    const float s = __ldg(&scl[gid >> 2]);
    float4 a = *(const float4*)(blk + base);
    float4 b = *(const float4*)(blk + base + 4);
    uint4 o;
    o.x = f2h2(a.x*s, a.y*s);
    o.y = f2h2(a.z*s, a.w*s);
    o.z = f2h2(b.x*s, b.y*s);
    o.w = f2h2(b.z*s, b.w*s);
    *(uint4*)(out + base) = o;
}

// ---------------- K0b: dequant down ----------------
__global__ void __launch_bounds__(256)
dequant_d(const float* __restrict__ dblk, const float* __restrict__ dscl)
{
    const size_t gid = (size_t)blockIdx.x * blockDim.x + threadIdx.x;
    const size_t base = gid * 8;
    const float s = __ldg(&dscl[gid >> 2]);
    float4 a = *(const float4*)(dblk + base);
    float4 b = *(const float4*)(dblk + base + 4);
    uint4 o;
    o.x = f2h2(a.x*s, a.y*s);
    o.y = f2h2(a.z*s, a.w*s);
    o.z = f2h2(b.x*s, b.y*s);
    o.w = f2h2(b.z*s, b.w*s);
    *(uint4*)(g_dw16 + base) = o;
}

// ---------------- K1: router (+ fp16 x emit + zero out row) ----------------
__global__ void router_kernel(const float* __restrict__ x,
                              const float* __restrict__ rw,
                              const float* __restrict__ rb,
                              float* __restrict__ out)
{
    __shared__ float sx[NH];
    __shared__ float slog[NEXP];
    const int t = blockIdx.x;
    for (int i = threadIdx.x; i < NH; i += blockDim.x)
        sx[i] = x[(size_t)t*NH + i];
    // zero this token's output row (atomic accumulation target)
    for (int i = threadIdx.x; i < NH/4; i += blockDim.x)
        ((float4*)(out + (size_t)t*NH))[i] = make_float4(0.f,0.f,0.f,0.f);
    __syncthreads();
    for (int i = threadIdx.x; i < NH/2; i += blockDim.x){
        *(uint32_t*)&g_xh[(size_t)t*NH + i*2] = f2h2(sx[i*2], sx[i*2+1]);
    }
    const int w = threadIdx.x >> 5;
    const int lane = threadIdx.x & 31;
    const float* wr = rw + (size_t)w*NH;
    float s = 0.f;
    for (int i = lane; i < NH; i += 32) s += sx[i]*wr[i];
    #pragma unroll
    for (int o=16;o>0;o>>=1) s += __shfl_xor_sync(0xffffffffu, s, o);
    if (lane==0) slog[w] = s + rb[w];
    __syncthreads();
    if (threadIdx.x==0){
        float v[NEXP];
        #pragma unroll
        for (int e=0;e<NEXP;e++) v[e]=slog[e];
        int idx[NTOP]; float val[NTOP];
        #pragma unroll
        for (int k=0;k<NTOP;k++){
            int bi=0; float bv=v[0];
            #pragma unroll
            for (int e=1;e<NEXP;e++){ if (v[e]>bv){bv=v[e];bi=e;} }
            idx[k]=bi; val[k]=bv; v[bi]=-3.4e38f;
        }
        float mx=val[0], ssum=0.f, ev[NTOP];
        #pragma unroll
        for(int k=0;k<NTOP;k++){ ev[k]=expf(val[k]-mx); ssum+=ev[k]; }
        float inv = 1.f/ssum;
        #pragma unroll
        for(int k=0;k<NTOP;k++){
            g_tok_exp[t*NTOP+k]=idx[k];
            g_tok_w[t*NTOP+k]=ev[k]*inv;
        }
    }
}

// ---------------- K2: build per-expert token lists (+ slot weights) ----------------
__global__ void build_lists_kernel()
{
    __shared__ int sc[NEXP], so[NEXP], scur[NEXP];
    const int t = threadIdx.x;
    if (t < NEXP) sc[t]=0;
    __syncthreads();
    int ex[NTOP];
    #pragma unroll
    for (int k=0;k<NTOP;k++){ ex[k]=g_tok_exp[t*NTOP+k]; atomicAdd(&sc[ex[k]],1); }
    __syncthreads();
    if (t==0){
        int acc=0;
        for(int e=0;e<NEXP;e++){ so[e]=acc; acc+=sc[e]; }
    }
    __syncthreads();
    if (t<NEXP){ g_counts[t]=sc[t]; g_offsets[t]=so[t]; scur[t]=so[t]; }
    __syncthreads();
    #pragma unroll
    for (int k=0;k<NTOP;k++){
        int slot = atomicAdd(&scur[ex[k]],1);
        g_token_list[slot]=t;
        g_slot_w[slot]=g_tok_w[t*NTOP+k];
        g_slot_of[t*NTOP+k]=slot;
    }
}

// ================= GEMM cores (fp16 A+B via cp.async): 256 thr, 8 warps =================

// ---------------- K3: gate+up GEMM + activation ----------------
__global__ void __launch_bounds__(256,2)
gateup_full(const float* __restrict__ gbia, const float* __restrict__ ubia)
{
    extern __shared__ float smf[];
    __shared__ int sTok[128];
    __shared__ float sGb[64], sUb[64];

    const int e   = blockIdx.y >> 3;
    const int mt  = blockIdx.y & 7;
    const int M   = g_counts[e];
    if (mt*128 >= M) return;
    const int Mrows = min(128, M - mt*128);
    const int off = g_offsets[e];
    const int n0  = blockIdx.x * 64;
    const int tid = threadIdx.x;
    const int wid = tid >> 5;
    const int lane = tid & 31;

    if (tid < 128){
        int ml = mt*128 + tid; if (ml > M-1) ml = M-1;
        sTok[tid] = g_token_list[off + ml];
    }
    if (tid < 64){
        sGb[tid] = gbia[(size_t)e*NI + n0 + tid];
        sUb[tid] = ubia[(size_t)e*NI + n0 + tid];
    }
    __syncthreads();

    const uint32_t smemBase = smem_u32(smf);
    const int r0s = tid >> 3;
    const int s  = tid & 7;

    const __half* srcA[4]; uint32_t offA[4];
    #pragma unroll
    for (int j=0;j<4;j++){
        int r = r0s + 32*j;
        srcA[j] = g_xh + (size_t)sTok[r]*NH + s*8;
        offA[j] = (uint32_t)(r*STRB + s*16);
    }
    const __half* srcB[4]; uint32_t offB[4];
    #pragma unroll
    for (int j=0;j<4;j++){
        int r = r0s + 32*j;
        const __half* w16 = (r < 64) ? g_gw16 : g_uw16;
        srcB[j] = w16 + ((size_t)e*NI + (size_t)(n0 + (r & 63)))*NH + s*8;
        offB[j] = (uint32_t)(ABYTES + r*STRB + s*16);
    }

    const int wm = (wid & 3) * 32;
    const int wn = (wid >> 2) * 32;
    const int fr = lane >> 2;
    const int fc = lane & 3;
    const bool active = (wm < Mrows);

    const uint32_t lmA0 = (uint32_t)((wm + (lane & 15))*STRB + (lane >> 4)*16);
    const uint32_t lmBg = (uint32_t)(ABYTES + (wn + ((lane>>4)&1)*8 + (lane&7))*STRB + ((lane>>3)&1)*16);

    float accg[2][4][4], accu[2][4][4];
    #pragma unroll
    for (int a=0;a<2;a++)
        #pragma unroll
        for (int b=0;b<4;b++)
            #pragma unroll
            for (int c=0;c<4;c++){ accg[a][b][c]=0.f; accu[a][b][c]=0.f; }

    #pragma unroll
    for (int st=0; st<2; st++){
        #pragma unroll
        for (int j=0;j<4;j++) cp16(smemBase + st*STAGEB + offA[j], srcA[j] + st*64);
        #pragma unroll
        for (int j=0;j<4;j++) cp16(smemBase + st*STAGEB + offB[j], srcB[j] + st*64);
        cp_commit();
    }
    cp_wait1();
    __syncthreads();

#define GU_MMA(ks) do { \
    uint32_t af[2][4]; \
    _Pragma("unroll") \
    for (int m2=0;m2<2;m2++) \
        ldsm4(af[m2][0],af[m2][1],af[m2][2],af[m2][3], stg + lmA0 + m2*2304 + (ks)*32); \
    uint32_t bg[4][2], bu[4][2]; \
    _Pragma("unroll") \
    for (int j=0;j<2;j++){ \
        ldsm4(bg[2*j][0],bg[2*j][1],bg[2*j+1][0],bg[2*j+1][1], stg + lmBg + j*2304 + (ks)*32); \
        ldsm4(bu[2*j][0],bu[2*j][1],bu[2*j+1][0],bu[2*j+1][1], stg + lmBg + 9216 + j*2304 + (ks)*32); \
    } \
    _Pragma("unroll") \
    for (int nt=0;nt<4;nt++) \
        _Pragma("unroll") \
        for (int m2=0;m2<2;m2++){ \
            mma_f16(accg[m2][nt], af[m2], bg[nt]); \
            mma_f16(accu[m2][nt], af[m2], bu[nt]); \
        } \
} while(0)

    for (int kc=0; kc<NCH; kc++){
        const uint32_t stg = smemBase + (kc%NSTG)*STAGEB;
        if (kc+2 < NCH){
            const uint32_t dst = smemBase + ((kc+2)%NSTG)*STAGEB;
            const int ka = (kc+2)*64;
            #pragma unroll
            for (int j=0;j<4;j++) cp16(dst + offA[j], srcA[j] + ka);
            #pragma unroll
            for (int j=0;j<4;j++) cp16(dst + offB[j], srcB[j] + ka);
        }
        cp_commit();
        if (active){ GU_MMA(0); GU_MMA(1); GU_MMA(2); GU_MMA(3); }
        cp_wait1();
        __syncthreads();
    }
#undef GU_MMA

    if (active){
        #pragma unroll
        for (int m2=0;m2<2;m2++){
            #pragma unroll
            for (int nt=0;nt<4;nt++){
                const int rl = wm + m2*16 + fr;
                const int cu = wn + nt*8 + fc*2;
                const float gb0 = sGb[cu], gb1 = sGb[cu+1];
                const float ub0 = sUb[cu], ub1 = sUb[cu+1];
                if (rl < Mrows){
                    float h0 = act_fn(accg[m2][nt][0]+gb0, accu[m2][nt][0]+ub0);
                    float h1 = act_fn(accg[m2][nt][1]+gb1, accu[m2][nt][1]+ub1);
                    *(uint32_t*)&g_hbuf[(size_t)(off + mt*128 + rl)*NI + n0 + cu] = f2h2(h0,h1);
                }
                if (rl+8 < Mrows){
                    float h0 = act_fn(accg[m2][nt][2]+gb0, accu[m2][nt][2]+ub0);
                    float h1 = act_fn(accg[m2][nt][3]+gb1, accu[m2][nt][3]+ub1);
                    *(uint32_t*)&g_hbuf[(size_t)(off + mt*128 + rl+8)*NI + n0 + cu] = f2h2(h0,h1);
                }
            }
        }
    }
}

// ---------------- K4: down GEMM + bias + fused weighted scatter ----------------
__global__ void __launch_bounds__(256,2)
down_kernel(const float* __restrict__ dbia, float* __restrict__ out)
{
    extern __shared__ float smf[];
    __shared__ float sDb[128];
    __shared__ int   sTk[128];
    __shared__ float sW[128];

    const int e   = blockIdx.y >> 3;
    const int mt  = blockIdx.y & 7;
    const int M   = g_counts[e];
    if (mt*128 >= M) return;
    const int Mrows = min(128, M - mt*128);
    const int off = g_offsets[e];
    const int n0  = blockIdx.x * 128;
    const int tid = threadIdx.x;
    const int wid = tid >> 5;
    const int lane = tid & 31;

    if (tid < 128){
        sDb[tid] = dbia[(size_t)e*NH + n0 + tid];
        int ml = mt*128 + tid; if (ml > M-1) ml = M-1;
        sTk[tid] = g_token_list[off + ml];
        sW[tid]  = g_slot_w[off + ml];
    }
    __syncthreads();

    const uint32_t smemBase = smem_u32(smf);
    const int r0s = tid >> 3;
    const int s  = tid & 7;

    const __half* srcA[4]; uint32_t offA[4];
    #pragma unroll
    for (int j=0;j<4;j++){
        int r = r0s + 32*j;
        int ml = mt*128 + r; if (ml > M-1) ml = M-1;
        srcA[j] = g_hbuf + (size_t)(off + ml)*NI + s*8;
        offA[j] = (uint32_t)(r*STRB + s*16);
    }
    const __half* srcB[4]; uint32_t offB[4];
    #pragma unroll
    for (int j=0;j<4;j++){
        int r = r0s + 32*j;
        srcB[j] = g_dw16 + ((size_t)e*NH + (size_t)(n0 + r))*NI + s*8;
        offB[j] = (uint32_t)(ABYTES + r*STRB + s*16);
    }

    const int wm = (wid & 3) * 32;
    const int wn = (wid >> 2) * 64;
    const int fr = lane >> 2;
    const int fc = lane & 3;
    const bool active = (wm < Mrows);

    const uint32_t lmA0 = (uint32_t)((wm + (lane & 15))*STRB + (lane >> 4)*16);
    const uint32_t lmB0 = (uint32_t)(ABYTES + (wn + ((lane>>4)&1)*8 + (lane&7))*STRB + ((lane>>3)&1)*16);

    float acc[2][8][4];
    #pragma unroll
    for (int a=0;a<2;a++)
        #pragma unroll
        for (int b=0;b<8;b++)
            #pragma unroll
            for (int c=0;c<4;c++) acc[a][b][c]=0.f;

    #pragma unroll
    for (int st=0; st<2; st++){
        #pragma unroll
        for (int j=0;j<4;j++) cp16(smemBase + st*STAGEB + offA[j], srcA[j] + st*64);
        #pragma unroll
        for (int j=0;j<4;j++) cp16(smemBase + st*STAGEB + offB[j], srcB[j] + st*64);
        cp_commit();
    }
    cp_wait1();
    __syncthreads();

#define DN_MMA(ks) do { \
    uint32_t af[2][4]; \
    _Pragma("unroll") \
    for (int m2=0;m2<2;m2++) \
        ldsm4(af[m2][0],af[m2][1],af[m2][2],af[m2][3], stg + lmA0 + m2*2304 + (ks)*32); \
    uint32_t bf[8][2]; \
    _Pragma("unroll") \
    for (int j=0;j<4;j++) \
        ldsm4(bf[2*j][0],bf[2*j][1],bf[2*j+1][0],bf[2*j+1][1], stg + lmB0 + j*2304 + (ks)*32); \
    _Pragma("unroll") \
    for (int nt=0;nt<8;nt++) \
        _Pragma("unroll") \
        for (int m2=0;m2<2;m2++) mma_f16(acc[m2][nt], af[m2], bf[nt]); \
} while(0)

    for (int kc=0; kc<NCH; kc++){
        const uint32_t stg = smemBase + (kc%NSTG)*STAGEB;
        if (kc+2 < NCH){
            const uint32_t dst = smemBase + ((kc+2)%NSTG)*STAGEB;
            const int ka = (kc+2)*64;
            #pragma unroll
            for (int j=0;j<4;j++) cp16(dst + offA[j], srcA[j] + ka);
            #pragma unroll
            for (int j=0;j<4;j++) cp16(dst + offB[j], srcB[j] + ka);
        }
        cp_commit();
        if (active){ DN_MMA(0); DN_MMA(1); DN_MMA(2); DN_MMA(3); }
        cp_wait1();
        __syncthreads();
    }
#undef DN_MMA

    if (active){
        #pragma unroll
        for (int m2=0;m2<2;m2++){
            const int rl0 = wm + m2*16 + fr;
            const int t0  = sTk[rl0];       const float w0 = sW[rl0];
            const int t1  = sTk[rl0+8];     const float w1 = sW[rl0+8];
            float* o0 = out + (size_t)t0*NH + n0;
            float* o1 = out + (size_t)t1*NH + n0;
            #pragma unroll
            for (int nt=0;nt<8;nt++){
                const int cg = wn + nt*8 + fc*2;
                const float b0 = sDb[cg], b1 = sDb[cg+1];
                if (rl0 < Mrows){
                    red_add(o0 + cg,     w0*(acc[m2][nt][0]+b0));
                    red_add(o0 + cg + 1, w0*(acc[m2][nt][1]+b1));
                }
                if (rl0+8 < Mrows){
                    red_add(o1 + cg,     w1*(acc[m2][nt][2]+b0));
                    red_add(o1 + cg + 1, w1*(acc[m2][nt][3]+b1));
                }
            }
        }
    }
}

// ---------------- launch: two-branch graph via event fork/join ----------------
extern "C" void kernel_launch(void* const* d_in, const int* in_sizes, int n_in,
                              void* d_out, int out_size)
{
    const float* x    = (const float*)d_in[0];
    const float* rw   = (const float*)d_in[1];
    const float* rb   = (const float*)d_in[2];
    const float* gblk = (const float*)d_in[3];
    const float* gscl = (const float*)d_in[4];
    const float* gbia = (const float*)d_in[5];
    const float* ublk = (const float*)d_in[6];
    const float* uscl = (const float*)d_in[7];
    const float* ubia = (const float*)d_in[8];
    const float* dblk = (const float*)d_in[9];
    const float* dscl = (const float*)d_in[10];
    const float* dbia = (const float*)d_in[11];
    float* out = (float*)d_out;

    static cudaStream_t s2 = nullptr;
    static cudaEvent_t eFork = nullptr, eL = nullptr, eG = nullptr, eD = nullptr;
    if (!s2){
        cudaStreamCreateWithFlags(&s2, cudaStreamNonBlocking);
        cudaEventCreateWithFlags(&eFork, cudaEventDisableTiming);
        cudaEventCreateWithFlags(&eL, cudaEventDisableTiming);
        cudaEventCreateWithFlags(&eG, cudaEventDisableTiming);
        cudaEventCreateWithFlags(&eD, cudaEventDisableTiming);
        cudaFuncSetAttribute(gateup_full, cudaFuncAttributeMaxDynamicSharedMemorySize, DSMEM_BYTES);
        cudaFuncSetAttribute(down_kernel, cudaFuncAttributeMaxDynamicSharedMemorySize, DSMEM_BYTES);
    }

    const int DQBLKS = (int)(WELEM / 8 / 256);   // 32768

    // fork side branch s2 from the main (default) stream
    cudaEventRecord(eFork, 0);
    cudaStreamWaitEvent(s2, eFork, 0);

    // branch B: router (+zero out) -> lists  [concurrent with dequant_gu]
    router_kernel<<<NT, 512, 0, s2>>>(x, rw, rb, out);
    build_lists_kernel<<<1, NT, 0, s2>>>();
    cudaEventRecord(eL, s2);

    // branch A: dequant gate+up
    dequant_gu<<<dim3(DQBLKS, 2), 256>>>(gblk, gscl, ublk, uscl);
    cudaEventRecord(eG, 0);

    // branch B continues: dequant_d overlapped with gateup
    cudaStreamWaitEvent(s2, eG, 0);
    dequant_d<<<DQBLKS, 256, 0, s2>>>(dblk, dscl);
    cudaEventRecord(eD, s2);

    // branch A: gateup (needs lists + dequant_gu)
    cudaStreamWaitEvent(0, eL, 0);
    gateup_full<<<dim3(NI/64, NEXP*8), 256, DSMEM_BYTES>>>(gbia, ubia);

    // join: down needs gateup + dequant_d (+ zeroed out)
    cudaStreamWaitEvent(0, eD, 0);
    down_kernel<<<dim3(NH/128, NEXP*8), 256, DSMEM_BYTES>>>(dbia, out);
}